// round 2
// baseline (speedup 1.0000x reference)
#include <cuda_runtime.h>

#define BB 16384
#define TT 16
#define II 256
#define HH 128
#define GG 512
#define EPSF 1e-5f

#define TM 64
#define TN 128
#define TK 64
#define BSLD 68          // 68 floats = 272 B row stride: 16B-aligned, 68%32==4 -> conflict-free LDS.128
#define NTH 512

// Scratch (device globals: allocation-free per harness rules)
__device__ float g_a[(size_t)BB * TT * GG];   // LN_x(x@W_ih^T)*g_x + b_x + b, per (b,t)
__device__ float g_cst[(size_t)BB * HH];      // cell state carry

__device__ __forceinline__ float sigm(float x) { return 1.f / (1.f + __expf(-x)); }

__device__ __forceinline__ void wred2(float& s, float& ss) {
#pragma unroll
    for (int o = 16; o > 0; o >>= 1) {
        s  += __shfl_xor_sync(0xffffffffu, s,  o);
        ss += __shfl_xor_sync(0xffffffffu, ss, o);
    }
}

// Tiled SGEMM: computes gts[TM][GG] = A[m0:m0+TM, :KDIM] * W[GG, KDIM]^T
// A rows at stride `astride` floats. Result left in shared `gts`.
template <int KDIM>
__device__ __forceinline__ void gemm_tile(const float* __restrict__ Abase, int astride,
                                          const float* __restrict__ Wbase,
                                          float* As, float* Bs, float* gts, int m0)
{
    const int tid  = threadIdx.x;
    const int lane = tid & 31;
    const int wp   = tid >> 5;

#pragma unroll 1
    for (int nc = 0; nc < GG / TN; ++nc) {
        float acc[4][4] = {};
#pragma unroll 1
        for (int kt = 0; kt < KDIM / TK; ++kt) {
            __syncthreads();
            // Load A tile: TM x TK
#pragma unroll
            for (int j = 0; j < (TM * TK / 4) / NTH; ++j) {
                int lin = tid + j * NTH;
                int rr = lin >> 4, kq = lin & 15;
                *(float4*)(As + rr * TK + kq * 4) =
                    *(const float4*)(Abase + (size_t)(m0 + rr) * astride + kt * TK + kq * 4);
            }
            // Load B tile: TN x TK (rows of W)
#pragma unroll
            for (int j = 0; j < (TN * TK / 4) / NTH; ++j) {
                int lin = tid + j * NTH;
                int cc = lin >> 4, kq = lin & 15;
                *(float4*)(Bs + cc * BSLD + kq * 4) =
                    *(const float4*)(Wbase + (size_t)(nc * TN + cc) * KDIM + kt * TK + kq * 4);
            }
            __syncthreads();
#pragma unroll
            for (int k = 0; k < TK; k += 4) {
                float4 av[4], bv[4];
#pragma unroll
                for (int r = 0; r < 4; ++r)
                    av[r] = *(const float4*)(As + (wp * 4 + r) * TK + k);  // warp-uniform broadcast
#pragma unroll
                for (int c = 0; c < 4; ++c)
                    bv[c] = *(const float4*)(Bs + (lane * 4 + c) * BSLD + k);
#pragma unroll
                for (int r = 0; r < 4; ++r)
#pragma unroll
                    for (int c = 0; c < 4; ++c) {
                        acc[r][c] += av[r].x * bv[c].x;
                        acc[r][c] += av[r].y * bv[c].y;
                        acc[r][c] += av[r].z * bv[c].z;
                        acc[r][c] += av[r].w * bv[c].w;
                    }
            }
        }
#pragma unroll
        for (int r = 0; r < 4; ++r) {
            float4 v = make_float4(acc[r][0], acc[r][1], acc[r][2], acc[r][3]);
            *(float4*)(gts + (wp * 4 + r) * GG + nc * TN + lane * 4) = v;
        }
    }
    __syncthreads();
}

// Kernel 1: a[b,t,:] = LN_pergate(x_t @ W_ih^T) * g_x + b_x + b
extern "C" __global__ void __launch_bounds__(NTH)
proj_kernel(const float* __restrict__ x, const float* __restrict__ W_ih,
            const float* __restrict__ bias, const float* __restrict__ g_x,
            const float* __restrict__ b_x)
{
    extern __shared__ float smem[];
    float* As  = smem;
    float* Bs  = smem + TM * TK;
    float* gts = smem + TM * TK + TN * BSLD;

    const int m0   = blockIdx.x * TM;
    gemm_tile<II>(x, II, W_ih, As, Bs, gts, m0);

    const int lane = threadIdx.x & 31;
    const int wp   = threadIdx.x >> 5;
#pragma unroll
    for (int rr = 0; rr < 4; ++rr) {
        const int row = wp * 4 + rr;
        const size_t m = (size_t)m0 + row;
#pragma unroll
        for (int q = 0; q < 4; ++q) {
            float v[4], s = 0.f, ss = 0.f;
#pragma unroll
            for (int j = 0; j < 4; ++j) {
                v[j] = gts[row * GG + q * HH + j * 32 + lane];
                s += v[j]; ss += v[j] * v[j];
            }
            wred2(s, ss);
            const float mu = s * (1.f / HH);
            const float rs = rsqrtf(ss * (1.f / HH) - mu * mu + EPSF);
#pragma unroll
            for (int j = 0; j < 4; ++j) {
                const int idx = q * HH + j * 32 + lane;
                g_a[m * GG + idx] = (v[j] - mu) * rs * g_x[idx] + b_x[idx] + bias[idx];
            }
        }
    }
}

// Kernel 2 (per timestep): gates = a_t + LN_pergate(h @ W_hh^T)*g_h + b_h; LSTM cell + cell-LN.
extern "C" __global__ void __launch_bounds__(NTH)
step_kernel(const float* __restrict__ hsrc, int hstride,
            const float* __restrict__ W_hh,
            const float* __restrict__ g_h, const float* __restrict__ b_h,
            const float* __restrict__ g_c, const float* __restrict__ b_c,
            const float* __restrict__ c0, int t, float* __restrict__ out,
            int write_hn)
{
    extern __shared__ float smem[];
    float* As  = smem;
    float* Bs  = smem + TM * TK;
    float* gts = smem + TM * TK + TN * BSLD;

    const int m0   = blockIdx.x * TM;
    gemm_tile<HH>(hsrc, hstride, W_hh, As, Bs, gts, m0);

    const int lane = threadIdx.x & 31;
    const int wp   = threadIdx.x >> 5;
#pragma unroll
    for (int rr = 0; rr < 4; ++rr) {
        const int row = wp * 4 + rr;
        const size_t bidx = (size_t)m0 + row;
        const float* arow = g_a + (bidx * TT + t) * GG;

        float gn[4][4];
#pragma unroll
        for (int q = 0; q < 4; ++q) {
            float v[4], s = 0.f, ss = 0.f;
#pragma unroll
            for (int j = 0; j < 4; ++j) {
                v[j] = gts[row * GG + q * HH + j * 32 + lane];
                s += v[j]; ss += v[j] * v[j];
            }
            wred2(s, ss);
            const float mu = s * (1.f / HH);
            const float rs = rsqrtf(ss * (1.f / HH) - mu * mu + EPSF);
#pragma unroll
            for (int j = 0; j < 4; ++j) {
                const int idx = q * HH + j * 32 + lane;
                gn[q][j] = (v[j] - mu) * rs * g_h[idx] + b_h[idx] + arow[idx];
            }
        }

        const float* csrc = (t == 0) ? c0 : g_cst;
        float cn[4], s = 0.f, ss = 0.f;
#pragma unroll
        for (int j = 0; j < 4; ++j) {
            const int hidx = j * 32 + lane;
            const float co = csrc[bidx * HH + hidx];
            const float iv = sigm(gn[0][j]);
            const float fv = sigm(gn[1][j]);
            const float gv = tanhf(gn[2][j]);
            cn[j] = fv * co + iv * gv;
            s += cn[j]; ss += cn[j] * cn[j];
        }
        wred2(s, ss);
        const float mu = s * (1.f / HH);
        const float rs = rsqrtf(ss * (1.f / HH) - mu * mu + EPSF);
#pragma unroll
        for (int j = 0; j < 4; ++j) {
            const int hidx = j * 32 + lane;
            const float cl = (cn[j] - mu) * rs * g_c[hidx] + b_c[hidx];
            const float hv = sigm(gn[3][j]) * tanhf(cl);
            g_cst[bidx * HH + hidx] = cn[j];
            out[(bidx * TT + t) * HH + hidx] = hv;
            if (write_hn)
                out[(size_t)BB * TT * HH + bidx * HH + hidx] = hv;
        }
    }
}

extern "C" void kernel_launch(void* const* d_in, const int* in_sizes, int n_in,
                              void* d_out, int out_size)
{
    const float* x    = (const float*)d_in[0];
    const float* h0   = (const float*)d_in[1];
    const float* c0   = (const float*)d_in[2];
    const float* W_ih = (const float*)d_in[3];
    const float* W_hh = (const float*)d_in[4];
    const float* bias = (const float*)d_in[5];
    const float* g_x  = (const float*)d_in[6];
    const float* b_x  = (const float*)d_in[7];
    const float* g_h  = (const float*)d_in[8];
    const float* b_h  = (const float*)d_in[9];
    const float* g_c  = (const float*)d_in[10];
    const float* b_c  = (const float*)d_in[11];
    float* out = (float*)d_out;

    const size_t smem = (size_t)(TM * TK + TN * BSLD + TM * GG) * sizeof(float); // ~178 KB
    cudaFuncSetAttribute(proj_kernel, cudaFuncAttributeMaxDynamicSharedMemorySize, (int)smem);
    cudaFuncSetAttribute(step_kernel, cudaFuncAttributeMaxDynamicSharedMemorySize, (int)smem);

    // Hoisted input projection + x-side gate LayerNorm for all timesteps
    proj_kernel<<<(BB * TT) / TM, NTH, smem>>>(x, W_ih, bias, g_x, b_x);

    const long long need = (long long)BB * TT * HH + (long long)BB * HH;
    const int write_full = (out_size >= need) ? 1 : 0;

    for (int t = 0; t < TT; ++t) {
        const float* hsrc = (t == 0) ? h0 : (out + (size_t)(t - 1) * HH);
        const int hstride = (t == 0) ? HH : TT * HH;
        step_kernel<<<BB / TM, NTH, smem>>>(hsrc, hstride, W_hh, g_h, b_h, g_c, b_c,
                                            c0, t, out, (t == TT - 1) ? write_full : 0);
    }
}

// round 3
// speedup vs baseline: 2.0288x; 2.0288x over previous
#include <cuda_runtime.h>

#define BB 16384
#define TT 16
#define II 256
#define HH 128
#define GG 512
#define EPSF 1e-5f

#define TM 32            // rows per block
#define TN 128           // one gate chunk per nc iteration
#define TK 64
#define BSLD 68          // 68 % 32 == 4 -> lane*68 spreads banks by 4 words: conflict-free LDS.128
#define NTH 256          // 8 warps, 4 rows each

// Scratch (device globals: allocation-free per harness rules)
__device__ float g_a[(size_t)BB * TT * GG];   // LN_x(x@W_ih^T)*g_x + b_x + b
__device__ float g_cst[(size_t)BB * HH];      // cell state carry

__device__ __forceinline__ float sigm(float x) { return 1.f / (1.f + __expf(-x)); }

__device__ __forceinline__ void wred2(float& s, float& ss) {
#pragma unroll
    for (int o = 16; o > 0; o >>= 1) {
        s  += __shfl_xor_sync(0xffffffffu, s,  o);
        ss += __shfl_xor_sync(0xffffffffu, ss, o);
    }
}

// ---------------------------------------------------------------------------
// Kernel 1: a[m,:] = LN_pergate(x_m @ W_ih^T) * g_x + b_x + b   (m = b*T + t)
// ---------------------------------------------------------------------------
extern "C" __global__ void __launch_bounds__(NTH, 2)
proj_kernel(const float* __restrict__ x, const float* __restrict__ W_ih,
            const float* __restrict__ bias, const float* __restrict__ g_x,
            const float* __restrict__ b_x)
{
    extern __shared__ float smem[];
    float* As = smem;                 // [TM][II]  32 KB
    float* Bs = smem + TM * II;       // [TN][BSLD] 34.8 KB

    const int tid  = threadIdx.x;
    const int lane = tid & 31;
    const int wp   = tid >> 5;
    const int m0   = blockIdx.x * TM;

    // A tile resident for full K=II
#pragma unroll
    for (int j = 0; j < (TM * II / 4) / NTH; ++j) {
        int lin = tid + j * NTH;
        int rr = lin >> 6, kq = lin & 63;           // II/4 = 64 float4 per row
        *(float4*)(As + rr * II + kq * 4) =
            *(const float4*)(x + (size_t)(m0 + rr) * II + kq * 4);
    }

#pragma unroll 1
    for (int nc = 0; nc < 4; ++nc) {
        float acc[4][4] = {};
#pragma unroll 1
        for (int kt = 0; kt < II / TK; ++kt) {
            __syncthreads();
#pragma unroll
            for (int j = 0; j < (TN * TK / 4) / NTH; ++j) {
                int lin = tid + j * NTH;
                int cc = lin >> 4, kq = lin & 15;
                *(float4*)(Bs + cc * BSLD + kq * 4) =
                    *(const float4*)(W_ih + (size_t)(nc * TN + cc) * II + kt * TK + kq * 4);
            }
            __syncthreads();
#pragma unroll
            for (int k = 0; k < TK; k += 4) {
                float4 av[4], bv[4];
#pragma unroll
                for (int r = 0; r < 4; ++r)
                    av[r] = *(const float4*)(As + (wp * 4 + r) * II + kt * TK + k); // uniform
#pragma unroll
                for (int c = 0; c < 4; ++c)
                    bv[c] = *(const float4*)(Bs + (c * 32 + lane) * BSLD + k);     // conflict-free
#pragma unroll
                for (int r = 0; r < 4; ++r)
#pragma unroll
                    for (int c = 0; c < 4; ++c) {
                        acc[r][c] += av[r].x * bv[c].x;
                        acc[r][c] += av[r].y * bv[c].y;
                        acc[r][c] += av[r].z * bv[c].z;
                        acc[r][c] += av[r].w * bv[c].w;
                    }
            }
        }
        // LN epilogue for this gate chunk, straight from registers
#pragma unroll
        for (int r = 0; r < 4; ++r) {
            float s = 0.f, ss = 0.f;
#pragma unroll
            for (int c = 0; c < 4; ++c) { s += acc[r][c]; ss += acc[r][c] * acc[r][c]; }
            wred2(s, ss);
            const float mu = s * (1.f / HH);
            const float rs = rsqrtf(ss * (1.f / HH) - mu * mu + EPSF);
            const size_t m = (size_t)m0 + wp * 4 + r;
#pragma unroll
            for (int c = 0; c < 4; ++c) {
                const int idx = nc * HH + c * 32 + lane;
                g_a[m * GG + idx] = (acc[r][c] - mu) * rs * g_x[idx] + b_x[idx] + bias[idx];
            }
        }
    }
}

// ---------------------------------------------------------------------------
// Kernel 2 (per timestep): gates = a_t + LN_pergate(h @ W_hh^T)*g_h + b_h;
// cell update + cell-LN + output gate, all in registers.
// ---------------------------------------------------------------------------
extern "C" __global__ void __launch_bounds__(NTH, 2)
step_kernel(const float* __restrict__ hsrc, int hstride,
            const float* __restrict__ W_hh,
            const float* __restrict__ g_h, const float* __restrict__ b_h,
            const float* __restrict__ g_c, const float* __restrict__ b_c,
            const float* __restrict__ c0, int t, float* __restrict__ out,
            int write_hn)
{
    extern __shared__ float smem[];
    float* As = smem;                 // [TM][HH]  16 KB
    float* Bs = smem + TM * HH;       // [TN][BSLD] 34.8 KB

    const int tid  = threadIdx.x;
    const int lane = tid & 31;
    const int wp   = tid >> 5;
    const int m0   = blockIdx.x * TM;

#pragma unroll
    for (int j = 0; j < (TM * HH / 4) / NTH; ++j) {
        int lin = tid + j * NTH;
        int rr = lin >> 5, kq = lin & 31;           // HH/4 = 32 float4 per row
        *(float4*)(As + rr * HH + kq * 4) =
            *(const float4*)(hsrc + (size_t)(m0 + rr) * hstride + kq * 4);
    }

    const float* csrc = (t == 0) ? c0 : g_cst;
    float iv[4][4];   // sigmoid(i) carry
    float cn[4][4];   // new cell state carry

#pragma unroll 1
    for (int nc = 0; nc < 4; ++nc) {
        float acc[4][4] = {};
#pragma unroll 1
        for (int kt = 0; kt < HH / TK; ++kt) {
            __syncthreads();
#pragma unroll
            for (int j = 0; j < (TN * TK / 4) / NTH; ++j) {
                int lin = tid + j * NTH;
                int cc = lin >> 4, kq = lin & 15;
                *(float4*)(Bs + cc * BSLD + kq * 4) =
                    *(const float4*)(W_hh + (size_t)(nc * TN + cc) * HH + kt * TK + kq * 4);
            }
            __syncthreads();
#pragma unroll
            for (int k = 0; k < TK; k += 4) {
                float4 av[4], bv[4];
#pragma unroll
                for (int r = 0; r < 4; ++r)
                    av[r] = *(const float4*)(As + (wp * 4 + r) * HH + kt * TK + k);
#pragma unroll
                for (int c = 0; c < 4; ++c)
                    bv[c] = *(const float4*)(Bs + (c * 32 + lane) * BSLD + k);
#pragma unroll
                for (int r = 0; r < 4; ++r)
#pragma unroll
                    for (int c = 0; c < 4; ++c) {
                        acc[r][c] += av[r].x * bv[c].x;
                        acc[r][c] += av[r].y * bv[c].y;
                        acc[r][c] += av[r].z * bv[c].z;
                        acc[r][c] += av[r].w * bv[c].w;
                    }
            }
        }
        // gate-LN + activation, folded chunk-by-chunk (i, f, g, o)
#pragma unroll
        for (int r = 0; r < 4; ++r) {
            float s = 0.f, ss = 0.f;
#pragma unroll
            for (int c = 0; c < 4; ++c) { s += acc[r][c]; ss += acc[r][c] * acc[r][c]; }
            wred2(s, ss);
            const float mu = s * (1.f / HH);
            const float rs = rsqrtf(ss * (1.f / HH) - mu * mu + EPSF);
            const size_t bidx = (size_t)m0 + wp * 4 + r;
            const float* arow = g_a + (bidx * TT + t) * GG;
#pragma unroll
            for (int c = 0; c < 4; ++c) {
                const int idx  = nc * HH + c * 32 + lane;
                const int hidx = c * 32 + lane;
                const float gn = (acc[r][c] - mu) * rs * g_h[idx] + b_h[idx] + arow[idx];
                if (nc == 0) {
                    iv[r][c] = sigm(gn);
                } else if (nc == 1) {
                    cn[r][c] = sigm(gn) * csrc[bidx * HH + hidx];
                } else if (nc == 2) {
                    cn[r][c] += iv[r][c] * tanhf(gn);
                } else {
                    iv[r][c] = sigm(gn);   // reuse as sigmoid(o)
                }
            }
        }
    }

    // cell-LN + output
#pragma unroll
    for (int r = 0; r < 4; ++r) {
        const size_t bidx = (size_t)m0 + wp * 4 + r;
        float s = 0.f, ss = 0.f;
#pragma unroll
        for (int c = 0; c < 4; ++c) { s += cn[r][c]; ss += cn[r][c] * cn[r][c]; }
        wred2(s, ss);
        const float mu = s * (1.f / HH);
        const float rs = rsqrtf(ss * (1.f / HH) - mu * mu + EPSF);
#pragma unroll
        for (int c = 0; c < 4; ++c) {
            const int hidx = c * 32 + lane;
            const float cl = (cn[r][c] - mu) * rs * g_c[hidx] + b_c[hidx];
            const float hv = iv[r][c] * tanhf(cl);
            g_cst[bidx * HH + hidx] = cn[r][c];
            out[(bidx * TT + t) * HH + hidx] = hv;
            if (write_hn)
                out[(size_t)BB * TT * HH + bidx * HH + hidx] = hv;
        }
    }
}

extern "C" void kernel_launch(void* const* d_in, const int* in_sizes, int n_in,
                              void* d_out, int out_size)
{
    const float* x    = (const float*)d_in[0];
    const float* h0   = (const float*)d_in[1];
    const float* c0   = (const float*)d_in[2];
    const float* W_ih = (const float*)d_in[3];
    const float* W_hh = (const float*)d_in[4];
    const float* bias = (const float*)d_in[5];
    const float* g_x  = (const float*)d_in[6];
    const float* b_x  = (const float*)d_in[7];
    const float* g_h  = (const float*)d_in[8];
    const float* b_h  = (const float*)d_in[9];
    const float* g_c  = (const float*)d_in[10];
    const float* b_c  = (const float*)d_in[11];
    float* out = (float*)d_out;

    const size_t smem_proj = (size_t)(TM * II + TN * BSLD) * sizeof(float); // ~66.8 KB
    const size_t smem_step = (size_t)(TM * HH + TN * BSLD) * sizeof(float); // ~51.2 KB
    static int configured = 0;
    cudaFuncSetAttribute(proj_kernel, cudaFuncAttributeMaxDynamicSharedMemorySize, (int)smem_proj);
    cudaFuncSetAttribute(step_kernel, cudaFuncAttributeMaxDynamicSharedMemorySize, (int)smem_step);
    (void)configured;

    proj_kernel<<<(BB * TT) / TM, NTH, smem_proj>>>(x, W_ih, bias, g_x, b_x);

    const long long need = (long long)BB * TT * HH + (long long)BB * HH;
    const int write_full = (out_size >= need) ? 1 : 0;

    for (int t = 0; t < TT; ++t) {
        const float* hsrc = (t == 0) ? h0 : (out + (size_t)(t - 1) * HH);
        const int hstride = (t == 0) ? HH : TT * HH;
        step_kernel<<<BB / TM, NTH, smem_step>>>(hsrc, hstride, W_hh, g_h, b_h, g_c, b_c,
                                                 c0, t, out, (t == TT - 1) ? write_full : 0);
    }
}

// round 6
// speedup vs baseline: 3.5532x; 1.7514x over previous
#include <cuda_runtime.h>
#include <cuda_bf16.h>
#include <cstdint>

#define BB 16384
#define TT 16
#define II 256
#define HH 128
#define GG 512
#define EPSF 1e-5f
#define NTH 256

// ---------------- scratch (device globals: allocation-free) ----------------
__device__ __align__(16) float g_a[(size_t)BB * TT * GG];   // LN_x(x@W_ih^T)*g_x + b_x + b
__device__ __align__(16) float g_cst[(size_t)BB * HH];      // cell state carry
__device__ __align__(16) __nv_bfloat16 g_wih_hi[GG * II], g_wih_lo[GG * II];
__device__ __align__(16) __nv_bfloat16 g_whh_hi[GG * HH], g_whh_lo[GG * HH];
__device__ __align__(16) __nv_bfloat16 g_h_hi[(size_t)BB * HH], g_h_lo[(size_t)BB * HH];

// ---------------- helpers ----------------
__device__ __forceinline__ uint32_t smem_u32(const void* p) {
    uint32_t a;
    asm("{ .reg .u64 t; cvta.to.shared.u64 t, %1; cvt.u32.u64 %0, t; }" : "=r"(a) : "l"(p));
    return a;
}
__device__ __forceinline__ void ldsm4(uint32_t* r, uint32_t a) {
    asm volatile("ldmatrix.sync.aligned.m8n8.x4.shared.b16 {%0,%1,%2,%3}, [%4];"
                 : "=r"(r[0]), "=r"(r[1]), "=r"(r[2]), "=r"(r[3]) : "r"(a));
}
__device__ __forceinline__ void mma16816(float* d, const uint32_t* a, uint32_t b0, uint32_t b1) {
    asm volatile(
        "mma.sync.aligned.m16n8k16.row.col.f32.bf16.bf16.f32 "
        "{%0,%1,%2,%3},{%4,%5,%6,%7},{%8,%9},{%0,%1,%2,%3};"
        : "+f"(d[0]), "+f"(d[1]), "+f"(d[2]), "+f"(d[3])
        : "r"(a[0]), "r"(a[1]), "r"(a[2]), "r"(a[3]), "r"(b0), "r"(b1));
}
__device__ __forceinline__ float qsum(float v) {
    v += __shfl_xor_sync(0xffffffffu, v, 1);
    v += __shfl_xor_sync(0xffffffffu, v, 2);
    return v;
}
__device__ __forceinline__ float sigm(float x) { return 1.f / (1.f + __expf(-x)); }
__device__ __forceinline__ uint32_t pack2(__nv_bfloat16 lo, __nv_bfloat16 hi) {
    return (uint32_t)__bfloat16_as_ushort(lo) | ((uint32_t)__bfloat16_as_ushort(hi) << 16);
}

// ---------------- smem layouts (bytes) ----------------
// step: A hi/lo [128 rows][136 bf16], B hi/lo [128 n][136 bf16]
#define ST_AHI 0
#define ST_ALO 34816
#define ST_BHI 69632
#define ST_BLO 104448
#define SMEM_STEP 139264
// proj: A hi/lo [128 rows][264 bf16] (K=256 resident), B hi/lo [128 n][136 bf16]
#define PJ_AHI 0
#define PJ_ALO 67584
#define PJ_BHI 135168
#define PJ_BLO 169984
#define SMEM_PROJ 204800

// ---------------- splitters (fp32 -> bf16 hi + bf16 residual) ----------------
extern "C" __global__ void split_wih(const float* __restrict__ s) {
    int i = blockIdx.x * blockDim.x + threadIdx.x;
    if (i < GG * II) {
        float v = s[i];
        __nv_bfloat16 h = __float2bfloat16(v);
        g_wih_hi[i] = h;
        g_wih_lo[i] = __float2bfloat16(v - __bfloat162float(h));
    }
}
extern "C" __global__ void split_whh(const float* __restrict__ s) {
    int i = blockIdx.x * blockDim.x + threadIdx.x;
    if (i < GG * HH) {
        float v = s[i];
        __nv_bfloat16 h = __float2bfloat16(v);
        g_whh_hi[i] = h;
        g_whh_lo[i] = __float2bfloat16(v - __bfloat162float(h));
    }
}
extern "C" __global__ void split_h0(const float* __restrict__ s) {
    int i = blockIdx.x * blockDim.x + threadIdx.x;
    if (i < BB * HH) {
        float v = s[i];
        __nv_bfloat16 h = __float2bfloat16(v);
        g_h_hi[i] = h;
        g_h_lo[i] = __float2bfloat16(v - __bfloat162float(h));
    }
}

// ---------------- proj: g_a = LN_pergate(x @ W_ih^T)*g_x + b_x + b ----------------
extern "C" __global__ void __launch_bounds__(NTH, 1)
proj_kernel(const float* __restrict__ x, const float* __restrict__ bias,
            const float* __restrict__ gx, const float* __restrict__ bx)
{
    extern __shared__ char smc[];
    const uint32_t sb = smem_u32(smc);
    const int tid = threadIdx.x, lane = tid & 31, wid = tid >> 5;
    const int m0 = blockIdx.x * 128;
    const int wr0 = wid * 16;

    // stage A: x[m0..+127][0..255] fp32 -> bf16 hi/lo (row stride 264 bf16 = 528 B)
#pragma unroll
    for (int it = 0; it < 16; ++it) {
        int c = tid + it * NTH;                 // 4096 chunks of 8 floats
        int row = c >> 5, k8 = (c & 31) * 8;
        const float* src = x + (size_t)(m0 + row) * II + k8;
        float4 v0 = *(const float4*)src, v1 = *(const float4*)(src + 4);
        __nv_bfloat16 h0 = __float2bfloat16(v0.x), h1 = __float2bfloat16(v0.y);
        __nv_bfloat16 h2 = __float2bfloat16(v0.z), h3 = __float2bfloat16(v0.w);
        __nv_bfloat16 h4 = __float2bfloat16(v1.x), h5 = __float2bfloat16(v1.y);
        __nv_bfloat16 h6 = __float2bfloat16(v1.z), h7 = __float2bfloat16(v1.w);
        uint4 hp, lp;
        hp.x = pack2(h0, h1); hp.y = pack2(h2, h3);
        hp.z = pack2(h4, h5); hp.w = pack2(h6, h7);
        lp.x = pack2(__float2bfloat16(v0.x - __bfloat162float(h0)),
                     __float2bfloat16(v0.y - __bfloat162float(h1)));
        lp.y = pack2(__float2bfloat16(v0.z - __bfloat162float(h2)),
                     __float2bfloat16(v0.w - __bfloat162float(h3)));
        lp.z = pack2(__float2bfloat16(v1.x - __bfloat162float(h4)),
                     __float2bfloat16(v1.y - __bfloat162float(h5)));
        lp.w = pack2(__float2bfloat16(v1.z - __bfloat162float(h6)),
                     __float2bfloat16(v1.w - __bfloat162float(h7)));
        *(uint4*)(smc + PJ_AHI + row * 528 + k8 * 2) = hp;
        *(uint4*)(smc + PJ_ALO + row * 528 + k8 * 2) = lp;
    }

    const int rA = wr0 + (lane >> 2);
    const size_t mA = (size_t)m0 + rA, mB = mA + 8;

    float acc[16][4];
#pragma unroll 1
    for (int gq = 0; gq < 4; ++gq) {
#pragma unroll
        for (int j = 0; j < 16; ++j) { acc[j][0] = acc[j][1] = acc[j][2] = acc[j][3] = 0.f; }
#pragma unroll 1
        for (int kh = 0; kh < 2; ++kh) {
            // stage B: W_ih [gq*128..+127][kh*128..+127]
#pragma unroll
            for (int it = 0; it < 8; ++it) {
                int c = tid + it * NTH;
                int n = c >> 4, k8 = (c & 15) * 8;
                size_t gi = (size_t)(gq * HH + n) * II + kh * HH + k8;
                *(uint4*)(smc + PJ_BHI + n * 272 + k8 * 2) = *(const uint4*)(g_wih_hi + gi);
                *(uint4*)(smc + PJ_BLO + n * 272 + k8 * 2) = *(const uint4*)(g_wih_lo + gi);
            }
            __syncthreads();
            const uint32_t abase = sb + PJ_AHI + (wr0 + (lane & 15)) * 528 + kh * 256 + (lane >> 4) * 16;
            const uint32_t bb0 = sb + PJ_BHI + ((lane & 7) + ((lane >> 4) << 3)) * 272 + (((lane >> 3) & 1) << 4);
#pragma unroll
            for (int ks = 0; ks < 8; ++ks) {
                uint32_t ah[4], al[4];
                ldsm4(ah, abase + ks * 32);
                ldsm4(al, abase + ks * 32 + (PJ_ALO - PJ_AHI));
#pragma unroll
                for (int g = 0; g < 8; ++g) {
                    uint32_t bh4[4], bl4[4];
                    uint32_t ba = bb0 + g * 16 * 272 + ks * 32;
                    ldsm4(bh4, ba);
                    ldsm4(bl4, ba + (PJ_BLO - PJ_BHI));
                    mma16816(acc[2 * g],     ah, bh4[0], bh4[1]);
                    mma16816(acc[2 * g + 1], ah, bh4[2], bh4[3]);
                    mma16816(acc[2 * g],     al, bh4[0], bh4[1]);
                    mma16816(acc[2 * g + 1], al, bh4[2], bh4[3]);
                    mma16816(acc[2 * g],     ah, bl4[0], bl4[1]);
                    mma16816(acc[2 * g + 1], ah, bl4[2], bl4[3]);
                }
            }
            __syncthreads();
        }
        // LN epilogue for this gate chunk
        float s0 = 0.f, q0 = 0.f, s1 = 0.f, q1 = 0.f;
#pragma unroll
        for (int j = 0; j < 16; ++j) {
            s0 += acc[j][0] + acc[j][1]; q0 += acc[j][0] * acc[j][0] + acc[j][1] * acc[j][1];
            s1 += acc[j][2] + acc[j][3]; q1 += acc[j][2] * acc[j][2] + acc[j][3] * acc[j][3];
        }
        s0 = qsum(s0); q0 = qsum(q0); s1 = qsum(s1); q1 = qsum(q1);
        const float mu0 = s0 * (1.f / HH), rs0 = rsqrtf(q0 * (1.f / HH) - mu0 * mu0 + EPSF);
        const float mu1 = s1 * (1.f / HH), rs1 = rsqrtf(q1 * (1.f / HH) - mu1 * mu1 + EPSF);
#pragma unroll
        for (int j = 0; j < 16; ++j)
#pragma unroll
            for (int e = 0; e < 4; ++e) {
                int col = 8 * j + 2 * (lane & 3) + (e & 1);
                int gcol = gq * HH + col;
                float mu = (e < 2) ? mu0 : mu1, rs = (e < 2) ? rs0 : rs1;
                size_t m = (e < 2) ? mA : mB;
                g_a[m * GG + gcol] = (acc[j][e] - mu) * rs * gx[gcol] + bx[gcol] + bias[gcol];
            }
    }
}

// ---------------- step: full LN-LSTM cell for one timestep ----------------
extern "C" __global__ void __launch_bounds__(NTH, 1)
step_kernel(const float* __restrict__ gh, const float* __restrict__ bh,
            const float* __restrict__ gc, const float* __restrict__ bc,
            const float* __restrict__ c0, int t, float* __restrict__ out,
            int write_hn)
{
    extern __shared__ char smc[];
    const uint32_t sb = smem_u32(smc);
    const int tid = threadIdx.x, lane = tid & 31, wid = tid >> 5;
    const int m0 = blockIdx.x * 128;
    const int wr0 = wid * 16;

    // stage A: h hi/lo [m0..+127][0..127], row stride 136 bf16 = 272 B
#pragma unroll
    for (int it = 0; it < 8; ++it) {
        int c = tid + it * NTH;
        int row = c >> 4, k8 = (c & 15) * 8;
        size_t gi = (size_t)(m0 + row) * HH + k8;
        *(uint4*)(smc + ST_AHI + row * 272 + k8 * 2) = *(const uint4*)(g_h_hi + gi);
        *(uint4*)(smc + ST_ALO + row * 272 + k8 * 2) = *(const uint4*)(g_h_lo + gi);
    }

    const int rA = wr0 + (lane >> 2);
    const size_t bidxA = (size_t)m0 + rA, bidxB = bidxA + 8;
    const float* arowA = g_a + (bidxA * TT + t) * GG;
    const float* arowB = g_a + (bidxB * TT + t) * GG;
    const float* csrc = (t == 0) ? c0 : (const float*)g_cst;

    float acc[16][4];
    float S[16][4];                              // sigma(i) -> sigma(i)*tanh(g) -> c_new
    float sc0 = 0.f, qc0 = 0.f, sc1 = 0.f, qc1 = 0.f;

#pragma unroll 1
    for (int p = 0; p < 4; ++p) {
        const int gq = (0x3120 >> (p * 4)) & 0xF;   // phase order: i(0), g(2), f(1), o(3)
        // stage B: W_hh [gq*128..+127][0..127]
#pragma unroll
        for (int it = 0; it < 8; ++it) {
            int c = tid + it * NTH;
            int n = c >> 4, k8 = (c & 15) * 8;
            size_t gi = (size_t)(gq * HH + n) * HH + k8;
            *(uint4*)(smc + ST_BHI + n * 272 + k8 * 2) = *(const uint4*)(g_whh_hi + gi);
            *(uint4*)(smc + ST_BLO + n * 272 + k8 * 2) = *(const uint4*)(g_whh_lo + gi);
        }
        __syncthreads();
#pragma unroll
        for (int j = 0; j < 16; ++j) { acc[j][0] = acc[j][1] = acc[j][2] = acc[j][3] = 0.f; }
        const uint32_t abase = sb + ST_AHI + (wr0 + (lane & 15)) * 272 + (lane >> 4) * 16;
        const uint32_t bb0 = sb + ST_BHI + ((lane & 7) + ((lane >> 4) << 3)) * 272 + (((lane >> 3) & 1) << 4);
#pragma unroll
        for (int ks = 0; ks < 8; ++ks) {
            uint32_t ah[4], al[4];
            ldsm4(ah, abase + ks * 32);
            ldsm4(al, abase + ks * 32 + (ST_ALO - ST_AHI));
#pragma unroll
            for (int g = 0; g < 8; ++g) {
                uint32_t bh4[4], bl4[4];
                uint32_t ba = bb0 + g * 16 * 272 + ks * 32;
                ldsm4(bh4, ba);
                ldsm4(bl4, ba + (ST_BLO - ST_BHI));
                mma16816(acc[2 * g],     ah, bh4[0], bh4[1]);
                mma16816(acc[2 * g + 1], ah, bh4[2], bh4[3]);
                mma16816(acc[2 * g],     al, bh4[0], bh4[1]);
                mma16816(acc[2 * g + 1], al, bh4[2], bh4[3]);
                mma16816(acc[2 * g],     ah, bl4[0], bl4[1]);
                mma16816(acc[2 * g + 1], ah, bl4[2], bl4[3]);
            }
        }
        __syncthreads();

        // gate-LN stats
        float s0 = 0.f, q0 = 0.f, s1 = 0.f, q1 = 0.f;
#pragma unroll
        for (int j = 0; j < 16; ++j) {
            s0 += acc[j][0] + acc[j][1]; q0 += acc[j][0] * acc[j][0] + acc[j][1] * acc[j][1];
            s1 += acc[j][2] + acc[j][3]; q1 += acc[j][2] * acc[j][2] + acc[j][3] * acc[j][3];
        }
        s0 = qsum(s0); q0 = qsum(q0); s1 = qsum(s1); q1 = qsum(q1);
        const float mu0 = s0 * (1.f / HH), rs0 = rsqrtf(q0 * (1.f / HH) - mu0 * mu0 + EPSF);
        const float mu1 = s1 * (1.f / HH), rs1 = rsqrtf(q1 * (1.f / HH) - mu1 * mu1 + EPSF);

        if (p == 0) {                        // i gate
#pragma unroll
            for (int j = 0; j < 16; ++j)
#pragma unroll
                for (int e = 0; e < 4; ++e) {
                    int col = 8 * j + 2 * (lane & 3) + (e & 1);
                    int gcol = col;          // gq = 0
                    float mu = (e < 2) ? mu0 : mu1, rs = (e < 2) ? rs0 : rs1;
                    const float* ar = (e < 2) ? arowA : arowB;
                    S[j][e] = sigm((acc[j][e] - mu) * rs * gh[gcol] + bh[gcol] + ar[gcol]);
                }
        } else if (p == 1) {                 // g gate (chunk 2)
#pragma unroll
            for (int j = 0; j < 16; ++j)
#pragma unroll
                for (int e = 0; e < 4; ++e) {
                    int col = 8 * j + 2 * (lane & 3) + (e & 1);
                    int gcol = 2 * HH + col;
                    float mu = (e < 2) ? mu0 : mu1, rs = (e < 2) ? rs0 : rs1;
                    const float* ar = (e < 2) ? arowA : arowB;
                    S[j][e] *= tanhf((acc[j][e] - mu) * rs * gh[gcol] + bh[gcol] + ar[gcol]);
                }
        } else if (p == 2) {                 // f gate (chunk 1): c_new = sigma(f)*c_prev + S
#pragma unroll
            for (int j = 0; j < 16; ++j)
#pragma unroll
                for (int e = 0; e < 4; ++e) {
                    int col = 8 * j + 2 * (lane & 3) + (e & 1);
                    int gcol = HH + col;
                    float mu = (e < 2) ? mu0 : mu1, rs = (e < 2) ? rs0 : rs1;
                    const float* ar = (e < 2) ? arowA : arowB;
                    size_t bi = (e < 2) ? bidxA : bidxB;
                    float fv = sigm((acc[j][e] - mu) * rs * gh[gcol] + bh[gcol] + ar[gcol]);
                    float cv = fv * csrc[bi * HH + col] + S[j][e];
                    S[j][e] = cv;
                    g_cst[bi * HH + col] = cv;
                    if (e < 2) { sc0 += cv; qc0 += cv * cv; } else { sc1 += cv; qc1 += cv * cv; }
                }
        } else {                             // o gate (chunk 3): sigma(o) kept in acc
#pragma unroll
            for (int j = 0; j < 16; ++j)
#pragma unroll
                for (int e = 0; e < 4; ++e) {
                    int col = 8 * j + 2 * (lane & 3) + (e & 1);
                    int gcol = 3 * HH + col;
                    float mu = (e < 2) ? mu0 : mu1, rs = (e < 2) ? rs0 : rs1;
                    const float* ar = (e < 2) ? arowA : arowB;
                    acc[j][e] = sigm((acc[j][e] - mu) * rs * gh[gcol] + bh[gcol] + ar[gcol]);
                }
        }
    }

    // cell-LN + output
    sc0 = qsum(sc0); qc0 = qsum(qc0); sc1 = qsum(sc1); qc1 = qsum(qc1);
    const float mc0 = sc0 * (1.f / HH), rc0 = rsqrtf(qc0 * (1.f / HH) - mc0 * mc0 + EPSF);
    const float mc1 = sc1 * (1.f / HH), rc1 = rsqrtf(qc1 * (1.f / HH) - mc1 * mc1 + EPSF);
    float* oA = out + (bidxA * TT + t) * HH;
    float* oB = out + (bidxB * TT + t) * HH;
#pragma unroll
    for (int j = 0; j < 16; ++j)
#pragma unroll
        for (int e = 0; e < 4; ++e) {
            int col = 8 * j + 2 * (lane & 3) + (e & 1);
            size_t bi = (e < 2) ? bidxA : bidxB;
            float mc = (e < 2) ? mc0 : mc1, rc = (e < 2) ? rc0 : rc1;
            float cl = (S[j][e] - mc) * rc * gc[col] + bc[col];
            float hv = acc[j][e] * tanhf(cl);
            ((e < 2) ? oA : oB)[col] = hv;
            __nv_bfloat16 hb = __float2bfloat16(hv);
            g_h_hi[bi * HH + col] = hb;
            g_h_lo[bi * HH + col] = __float2bfloat16(hv - __bfloat162float(hb));
            if (write_hn) out[(size_t)BB * TT * HH + bi * HH + col] = hv;
        }
}

// ---------------- host ----------------
extern "C" void kernel_launch(void* const* d_in, const int* in_sizes, int n_in,
                              void* d_out, int out_size)
{
    const float* x    = (const float*)d_in[0];
    const float* h0   = (const float*)d_in[1];
    const float* c0   = (const float*)d_in[2];
    const float* W_ih = (const float*)d_in[3];
    const float* W_hh = (const float*)d_in[4];
    const float* bias = (const float*)d_in[5];
    const float* g_x  = (const float*)d_in[6];
    const float* b_x  = (const float*)d_in[7];
    const float* gh   = (const float*)d_in[8];
    const float* bh   = (const float*)d_in[9];
    const float* gc   = (const float*)d_in[10];
    const float* bc   = (const float*)d_in[11];
    float* out = (float*)d_out;

    cudaFuncSetAttribute(proj_kernel, cudaFuncAttributeMaxDynamicSharedMemorySize, SMEM_PROJ);
    cudaFuncSetAttribute(step_kernel, cudaFuncAttributeMaxDynamicSharedMemorySize, SMEM_STEP);

    split_wih<<<(GG * II + 255) / 256, 256>>>(W_ih);
    split_whh<<<(GG * HH + 255) / 256, 256>>>(W_hh);
    split_h0<<<(BB * HH + 255) / 256, 256>>>(h0);

    proj_kernel<<<(BB * TT) / 128, NTH, SMEM_PROJ>>>(x, bias, g_x, b_x);

    const long long need = (long long)BB * TT * HH + (long long)BB * HH;
    const int write_full = (out_size >= need) ? 1 : 0;

    for (int t = 0; t < TT; ++t)
        step_kernel<<<BB / 128, NTH, SMEM_STEP>>>(gh, bh, gc, bc, c0, t, out,
                                                  (t == TT - 1) ? write_full : 0);
}

// round 7
// speedup vs baseline: 3.5636x; 1.0029x over previous
#include <cuda_runtime.h>
#include <cuda_bf16.h>
#include <cstdint>

#define BB 16384
#define TT 16
#define II 256
#define HH 128
#define GG 512
#define EPSF 1e-5f
#define NTH 256

// ---------------- scratch (device globals: allocation-free) ----------------
__device__ __align__(16) float g_a[(size_t)BB * TT * GG];   // LN_x(x@W_ih^T)*g_x + b_x + b
__device__ __align__(16) float g_cst[(size_t)BB * HH];      // cell state carry
__device__ __align__(16) __nv_bfloat16 g_wih_hi[GG * II], g_wih_lo[GG * II];
__device__ __align__(16) __nv_bfloat16 g_whh_hi[GG * HH], g_whh_lo[GG * HH];
__device__ __align__(16) __nv_bfloat16 g_h_hi[(size_t)BB * HH], g_h_lo[(size_t)BB * HH];

// ---------------- helpers ----------------
__device__ __forceinline__ uint32_t smem_u32(const void* p) {
    uint32_t a;
    asm("{ .reg .u64 t; cvta.to.shared.u64 t, %1; cvt.u32.u64 %0, t; }" : "=r"(a) : "l"(p));
    return a;
}
__device__ __forceinline__ void ldsm4(uint32_t* r, uint32_t a) {
    asm volatile("ldmatrix.sync.aligned.m8n8.x4.shared.b16 {%0,%1,%2,%3}, [%4];"
                 : "=r"(r[0]), "=r"(r[1]), "=r"(r[2]), "=r"(r[3]) : "r"(a));
}
__device__ __forceinline__ void mma16816(float* d, const uint32_t* a, uint32_t b0, uint32_t b1) {
    asm volatile(
        "mma.sync.aligned.m16n8k16.row.col.f32.bf16.bf16.f32 "
        "{%0,%1,%2,%3},{%4,%5,%6,%7},{%8,%9},{%0,%1,%2,%3};"
        : "+f"(d[0]), "+f"(d[1]), "+f"(d[2]), "+f"(d[3])
        : "r"(a[0]), "r"(a[1]), "r"(a[2]), "r"(a[3]), "r"(b0), "r"(b1));
}
__device__ __forceinline__ float qsum(float v) {
    v += __shfl_xor_sync(0xffffffffu, v, 1);
    v += __shfl_xor_sync(0xffffffffu, v, 2);
    return v;
}
__device__ __forceinline__ float sigm(float x) { return 1.f / (1.f + __expf(-x)); }
__device__ __forceinline__ uint32_t pack2(__nv_bfloat16 lo, __nv_bfloat16 hi) {
    return (uint32_t)__bfloat16_as_ushort(lo) | ((uint32_t)__bfloat16_as_ushort(hi) << 16);
}

// ---------------- smem layouts (bytes) ----------------
// step: A hi/lo [128 rows][136 bf16], B hi/lo [128 n][136 bf16]
#define ST_AHI 0
#define ST_ALO 34816
#define ST_BHI 69632
#define ST_BLO 104448
#define SMEM_STEP 139264
// proj: A hi/lo [128 rows][264 bf16] (K=256 resident), B hi/lo [128 n][136 bf16]
#define PJ_AHI 0
#define PJ_ALO 67584
#define PJ_BHI 135168
#define PJ_BLO 169984
#define SMEM_PROJ 204800

// ---------------- splitters (fp32 -> bf16 hi + bf16 residual) ----------------
extern "C" __global__ void split_wih(const float* __restrict__ s) {
    int i = blockIdx.x * blockDim.x + threadIdx.x;
    if (i < GG * II) {
        float v = s[i];
        __nv_bfloat16 h = __float2bfloat16(v);
        g_wih_hi[i] = h;
        g_wih_lo[i] = __float2bfloat16(v - __bfloat162float(h));
    }
}
extern "C" __global__ void split_whh(const float* __restrict__ s) {
    int i = blockIdx.x * blockDim.x + threadIdx.x;
    if (i < GG * HH) {
        float v = s[i];
        __nv_bfloat16 h = __float2bfloat16(v);
        g_whh_hi[i] = h;
        g_whh_lo[i] = __float2bfloat16(v - __bfloat162float(h));
    }
}
extern "C" __global__ void split_h0(const float* __restrict__ s) {
    int i = blockIdx.x * blockDim.x + threadIdx.x;
    if (i < BB * HH) {
        float v = s[i];
        __nv_bfloat16 h = __float2bfloat16(v);
        g_h_hi[i] = h;
        g_h_lo[i] = __float2bfloat16(v - __bfloat162float(h));
    }
}

// ---------------- proj: g_a = LN_pergate(x @ W_ih^T)*g_x + b_x + b ----------------
extern "C" __global__ void __launch_bounds__(NTH, 1)
proj_kernel(const float* __restrict__ x, const float* __restrict__ bias,
            const float* __restrict__ gx, const float* __restrict__ bx)
{
    extern __shared__ char smc[];
    const uint32_t sb = smem_u32(smc);
    const int tid = threadIdx.x, lane = tid & 31, wid = tid >> 5;
    const int m0 = blockIdx.x * 128;
    const int wr0 = wid * 16;

    // stage A: x[m0..+127][0..255] fp32 -> bf16 hi/lo (row stride 264 bf16 = 528 B)
#pragma unroll
    for (int it = 0; it < 16; ++it) {
        int c = tid + it * NTH;                 // 4096 chunks of 8 floats
        int row = c >> 5, k8 = (c & 31) * 8;
        const float* src = x + (size_t)(m0 + row) * II + k8;
        float4 v0 = *(const float4*)src, v1 = *(const float4*)(src + 4);
        __nv_bfloat16 h0 = __float2bfloat16(v0.x), h1 = __float2bfloat16(v0.y);
        __nv_bfloat16 h2 = __float2bfloat16(v0.z), h3 = __float2bfloat16(v0.w);
        __nv_bfloat16 h4 = __float2bfloat16(v1.x), h5 = __float2bfloat16(v1.y);
        __nv_bfloat16 h6 = __float2bfloat16(v1.z), h7 = __float2bfloat16(v1.w);
        uint4 hp, lp;
        hp.x = pack2(h0, h1); hp.y = pack2(h2, h3);
        hp.z = pack2(h4, h5); hp.w = pack2(h6, h7);
        lp.x = pack2(__float2bfloat16(v0.x - __bfloat162float(h0)),
                     __float2bfloat16(v0.y - __bfloat162float(h1)));
        lp.y = pack2(__float2bfloat16(v0.z - __bfloat162float(h2)),
                     __float2bfloat16(v0.w - __bfloat162float(h3)));
        lp.z = pack2(__float2bfloat16(v1.x - __bfloat162float(h4)),
                     __float2bfloat16(v1.y - __bfloat162float(h5)));
        lp.w = pack2(__float2bfloat16(v1.z - __bfloat162float(h6)),
                     __float2bfloat16(v1.w - __bfloat162float(h7)));
        *(uint4*)(smc + PJ_AHI + row * 528 + k8 * 2) = hp;
        *(uint4*)(smc + PJ_ALO + row * 528 + k8 * 2) = lp;
    }

    const int rA = wr0 + (lane >> 2);
    const size_t mA = (size_t)m0 + rA, mB = mA + 8;

    float acc[16][4];
#pragma unroll 1
    for (int gq = 0; gq < 4; ++gq) {
#pragma unroll
        for (int j = 0; j < 16; ++j) { acc[j][0] = acc[j][1] = acc[j][2] = acc[j][3] = 0.f; }
#pragma unroll 1
        for (int kh = 0; kh < 2; ++kh) {
            // stage B: W_ih [gq*128..+127][kh*128..+127]
#pragma unroll
            for (int it = 0; it < 8; ++it) {
                int c = tid + it * NTH;
                int n = c >> 4, k8 = (c & 15) * 8;
                size_t gi = (size_t)(gq * HH + n) * II + kh * HH + k8;
                *(uint4*)(smc + PJ_BHI + n * 272 + k8 * 2) = *(const uint4*)(g_wih_hi + gi);
                *(uint4*)(smc + PJ_BLO + n * 272 + k8 * 2) = *(const uint4*)(g_wih_lo + gi);
            }
            __syncthreads();
            const uint32_t abase = sb + PJ_AHI + (wr0 + (lane & 15)) * 528 + kh * 256 + (lane >> 4) * 16;
            const uint32_t bb0 = sb + PJ_BHI + ((lane & 7) + ((lane >> 4) << 3)) * 272 + (((lane >> 3) & 1) << 4);
#pragma unroll
            for (int ks = 0; ks < 8; ++ks) {
                uint32_t ah[4], al[4];
                ldsm4(ah, abase + ks * 32);
                ldsm4(al, abase + ks * 32 + (PJ_ALO - PJ_AHI));
#pragma unroll
                for (int g = 0; g < 8; ++g) {
                    uint32_t bh4[4], bl4[4];
                    uint32_t ba = bb0 + g * 16 * 272 + ks * 32;
                    ldsm4(bh4, ba);
                    ldsm4(bl4, ba + (PJ_BLO - PJ_BHI));
                    mma16816(acc[2 * g],     ah, bh4[0], bh4[1]);
                    mma16816(acc[2 * g + 1], ah, bh4[2], bh4[3]);
                    mma16816(acc[2 * g],     al, bh4[0], bh4[1]);
                    mma16816(acc[2 * g + 1], al, bh4[2], bh4[3]);
                    mma16816(acc[2 * g],     ah, bl4[0], bl4[1]);
                    mma16816(acc[2 * g + 1], ah, bl4[2], bl4[3]);
                }
            }
            __syncthreads();
        }
        // LN epilogue for this gate chunk
        float s0 = 0.f, q0 = 0.f, s1 = 0.f, q1 = 0.f;
#pragma unroll
        for (int j = 0; j < 16; ++j) {
            s0 += acc[j][0] + acc[j][1]; q0 += acc[j][0] * acc[j][0] + acc[j][1] * acc[j][1];
            s1 += acc[j][2] + acc[j][3]; q1 += acc[j][2] * acc[j][2] + acc[j][3] * acc[j][3];
        }
        s0 = qsum(s0); q0 = qsum(q0); s1 = qsum(s1); q1 = qsum(q1);
        const float mu0 = s0 * (1.f / HH), rs0 = rsqrtf(q0 * (1.f / HH) - mu0 * mu0 + EPSF);
        const float mu1 = s1 * (1.f / HH), rs1 = rsqrtf(q1 * (1.f / HH) - mu1 * mu1 + EPSF);
#pragma unroll
        for (int j = 0; j < 16; ++j)
#pragma unroll
            for (int e = 0; e < 4; ++e) {
                int col = 8 * j + 2 * (lane & 3) + (e & 1);
                int gcol = gq * HH + col;
                float mu = (e < 2) ? mu0 : mu1, rs = (e < 2) ? rs0 : rs1;
                size_t m = (e < 2) ? mA : mB;
                g_a[m * GG + gcol] = (acc[j][e] - mu) * rs * gx[gcol] + bx[gcol] + bias[gcol];
            }
    }
}

// ---------------- step: full LN-LSTM cell for one timestep ----------------
extern "C" __global__ void __launch_bounds__(NTH, 1)
step_kernel(const float* __restrict__ gh, const float* __restrict__ bh,
            const float* __restrict__ gc, const float* __restrict__ bc,
            const float* __restrict__ c0, int t, float* __restrict__ out,
            int write_hn)
{
    extern __shared__ char smc[];
    const uint32_t sb = smem_u32(smc);
    const int tid = threadIdx.x, lane = tid & 31, wid = tid >> 5;
    const int m0 = blockIdx.x * 128;
    const int wr0 = wid * 16;

    // stage A: h hi/lo [m0..+127][0..127], row stride 136 bf16 = 272 B
#pragma unroll
    for (int it = 0; it < 8; ++it) {
        int c = tid + it * NTH;
        int row = c >> 4, k8 = (c & 15) * 8;
        size_t gi = (size_t)(m0 + row) * HH + k8;
        *(uint4*)(smc + ST_AHI + row * 272 + k8 * 2) = *(const uint4*)(g_h_hi + gi);
        *(uint4*)(smc + ST_ALO + row * 272 + k8 * 2) = *(const uint4*)(g_h_lo + gi);
    }

    const int rA = wr0 + (lane >> 2);
    const size_t bidxA = (size_t)m0 + rA, bidxB = bidxA + 8;
    const float* arowA = g_a + (bidxA * TT + t) * GG;
    const float* arowB = g_a + (bidxB * TT + t) * GG;
    const float* csrc = (t == 0) ? c0 : (const float*)g_cst;

    float acc[16][4];
    float S[16][4];                              // sigma(i) -> sigma(i)*tanh(g) -> c_new
    float sc0 = 0.f, qc0 = 0.f, sc1 = 0.f, qc1 = 0.f;

#pragma unroll 1
    for (int p = 0; p < 4; ++p) {
        const int gq = (0x3120 >> (p * 4)) & 0xF;   // phase order: i(0), g(2), f(1), o(3)
        // stage B: W_hh [gq*128..+127][0..127]
#pragma unroll
        for (int it = 0; it < 8; ++it) {
            int c = tid + it * NTH;
            int n = c >> 4, k8 = (c & 15) * 8;
            size_t gi = (size_t)(gq * HH + n) * HH + k8;
            *(uint4*)(smc + ST_BHI + n * 272 + k8 * 2) = *(const uint4*)(g_whh_hi + gi);
            *(uint4*)(smc + ST_BLO + n * 272 + k8 * 2) = *(const uint4*)(g_whh_lo + gi);
        }
        __syncthreads();
#pragma unroll
        for (int j = 0; j < 16; ++j) { acc[j][0] = acc[j][1] = acc[j][2] = acc[j][3] = 0.f; }
        const uint32_t abase = sb + ST_AHI + (wr0 + (lane & 15)) * 272 + (lane >> 4) * 16;
        const uint32_t bb0 = sb + ST_BHI + ((lane & 7) + ((lane >> 4) << 3)) * 272 + (((lane >> 3) & 1) << 4);
#pragma unroll
        for (int ks = 0; ks < 8; ++ks) {
            uint32_t ah[4], al[4];
            ldsm4(ah, abase + ks * 32);
            ldsm4(al, abase + ks * 32 + (ST_ALO - ST_AHI));
#pragma unroll
            for (int g = 0; g < 8; ++g) {
                uint32_t bh4[4], bl4[4];
                uint32_t ba = bb0 + g * 16 * 272 + ks * 32;
                ldsm4(bh4, ba);
                ldsm4(bl4, ba + (ST_BLO - ST_BHI));
                mma16816(acc[2 * g],     ah, bh4[0], bh4[1]);
                mma16816(acc[2 * g + 1], ah, bh4[2], bh4[3]);
                mma16816(acc[2 * g],     al, bh4[0], bh4[1]);
                mma16816(acc[2 * g + 1], al, bh4[2], bh4[3]);
                mma16816(acc[2 * g],     ah, bl4[0], bl4[1]);
                mma16816(acc[2 * g + 1], ah, bl4[2], bl4[3]);
            }
        }
        __syncthreads();

        // gate-LN stats
        float s0 = 0.f, q0 = 0.f, s1 = 0.f, q1 = 0.f;
#pragma unroll
        for (int j = 0; j < 16; ++j) {
            s0 += acc[j][0] + acc[j][1]; q0 += acc[j][0] * acc[j][0] + acc[j][1] * acc[j][1];
            s1 += acc[j][2] + acc[j][3]; q1 += acc[j][2] * acc[j][2] + acc[j][3] * acc[j][3];
        }
        s0 = qsum(s0); q0 = qsum(q0); s1 = qsum(s1); q1 = qsum(q1);
        const float mu0 = s0 * (1.f / HH), rs0 = rsqrtf(q0 * (1.f / HH) - mu0 * mu0 + EPSF);
        const float mu1 = s1 * (1.f / HH), rs1 = rsqrtf(q1 * (1.f / HH) - mu1 * mu1 + EPSF);

        if (p == 0) {                        // i gate
#pragma unroll
            for (int j = 0; j < 16; ++j)
#pragma unroll
                for (int e = 0; e < 4; ++e) {
                    int col = 8 * j + 2 * (lane & 3) + (e & 1);
                    int gcol = col;          // gq = 0
                    float mu = (e < 2) ? mu0 : mu1, rs = (e < 2) ? rs0 : rs1;
                    const float* ar = (e < 2) ? arowA : arowB;
                    S[j][e] = sigm((acc[j][e] - mu) * rs * gh[gcol] + bh[gcol] + ar[gcol]);
                }
        } else if (p == 1) {                 // g gate (chunk 2)
#pragma unroll
            for (int j = 0; j < 16; ++j)
#pragma unroll
                for (int e = 0; e < 4; ++e) {
                    int col = 8 * j + 2 * (lane & 3) + (e & 1);
                    int gcol = 2 * HH + col;
                    float mu = (e < 2) ? mu0 : mu1, rs = (e < 2) ? rs0 : rs1;
                    const float* ar = (e < 2) ? arowA : arowB;
                    S[j][e] *= tanhf((acc[j][e] - mu) * rs * gh[gcol] + bh[gcol] + ar[gcol]);
                }
        } else if (p == 2) {                 // f gate (chunk 1): c_new = sigma(f)*c_prev + S
#pragma unroll
            for (int j = 0; j < 16; ++j)
#pragma unroll
                for (int e = 0; e < 4; ++e) {
                    int col = 8 * j + 2 * (lane & 3) + (e & 1);
                    int gcol = HH + col;
                    float mu = (e < 2) ? mu0 : mu1, rs = (e < 2) ? rs0 : rs1;
                    const float* ar = (e < 2) ? arowA : arowB;
                    size_t bi = (e < 2) ? bidxA : bidxB;
                    float fv = sigm((acc[j][e] - mu) * rs * gh[gcol] + bh[gcol] + ar[gcol]);
                    float cv = fv * csrc[bi * HH + col] + S[j][e];
                    S[j][e] = cv;
                    g_cst[bi * HH + col] = cv;
                    if (e < 2) { sc0 += cv; qc0 += cv * cv; } else { sc1 += cv; qc1 += cv * cv; }
                }
        } else {                             // o gate (chunk 3): sigma(o) kept in acc
#pragma unroll
            for (int j = 0; j < 16; ++j)
#pragma unroll
                for (int e = 0; e < 4; ++e) {
                    int col = 8 * j + 2 * (lane & 3) + (e & 1);
                    int gcol = 3 * HH + col;
                    float mu = (e < 2) ? mu0 : mu1, rs = (e < 2) ? rs0 : rs1;
                    const float* ar = (e < 2) ? arowA : arowB;
                    acc[j][e] = sigm((acc[j][e] - mu) * rs * gh[gcol] + bh[gcol] + ar[gcol]);
                }
        }
    }

    // cell-LN + output
    sc0 = qsum(sc0); qc0 = qsum(qc0); sc1 = qsum(sc1); qc1 = qsum(qc1);
    const float mc0 = sc0 * (1.f / HH), rc0 = rsqrtf(qc0 * (1.f / HH) - mc0 * mc0 + EPSF);
    const float mc1 = sc1 * (1.f / HH), rc1 = rsqrtf(qc1 * (1.f / HH) - mc1 * mc1 + EPSF);
    float* oA = out + (bidxA * TT + t) * HH;
    float* oB = out + (bidxB * TT + t) * HH;
#pragma unroll
    for (int j = 0; j < 16; ++j)
#pragma unroll
        for (int e = 0; e < 4; ++e) {
            int col = 8 * j + 2 * (lane & 3) + (e & 1);
            size_t bi = (e < 2) ? bidxA : bidxB;
            float mc = (e < 2) ? mc0 : mc1, rc = (e < 2) ? rc0 : rc1;
            float cl = (S[j][e] - mc) * rc * gc[col] + bc[col];
            float hv = acc[j][e] * tanhf(cl);
            ((e < 2) ? oA : oB)[col] = hv;
            __nv_bfloat16 hb = __float2bfloat16(hv);
            g_h_hi[bi * HH + col] = hb;
            g_h_lo[bi * HH + col] = __float2bfloat16(hv - __bfloat162float(hb));
            if (write_hn) out[(size_t)BB * TT * HH + bi * HH + col] = hv;
        }
}

// ---------------- host ----------------
extern "C" void kernel_launch(void* const* d_in, const int* in_sizes, int n_in,
                              void* d_out, int out_size)
{
    const float* x    = (const float*)d_in[0];
    const float* h0   = (const float*)d_in[1];
    const float* c0   = (const float*)d_in[2];
    const float* W_ih = (const float*)d_in[3];
    const float* W_hh = (const float*)d_in[4];
    const float* bias = (const float*)d_in[5];
    const float* g_x  = (const float*)d_in[6];
    const float* b_x  = (const float*)d_in[7];
    const float* gh   = (const float*)d_in[8];
    const float* bh   = (const float*)d_in[9];
    const float* gc   = (const float*)d_in[10];
    const float* bc   = (const float*)d_in[11];
    float* out = (float*)d_out;

    cudaFuncSetAttribute(proj_kernel, cudaFuncAttributeMaxDynamicSharedMemorySize, SMEM_PROJ);
    cudaFuncSetAttribute(step_kernel, cudaFuncAttributeMaxDynamicSharedMemorySize, SMEM_STEP);

    split_wih<<<(GG * II + 255) / 256, 256>>>(W_ih);
    split_whh<<<(GG * HH + 255) / 256, 256>>>(W_hh);
    split_h0<<<(BB * HH + 255) / 256, 256>>>(h0);

    proj_kernel<<<(BB * TT) / 128, NTH, SMEM_PROJ>>>(x, bias, g_x, b_x);

    const long long need = (long long)BB * TT * HH + (long long)BB * HH;
    const int write_full = (out_size >= need) ? 1 : 0;

    for (int t = 0; t < TT; ++t)
        step_kernel<<<BB / 128, NTH, SMEM_STEP>>>(gh, bh, gc, bc, c0, t, out,
                                                  (t == TT - 1) ? write_full : 0);
}

// round 8
// speedup vs baseline: 4.2742x; 1.1994x over previous
#include <cuda_runtime.h>
#include <cuda_bf16.h>
#include <cstdint>

#define BB 16384
#define TT 16
#define II 256
#define HH 128
#define GG 512
#define EPSF 1e-5f
#define NTH 256

// ---------------- scratch (device globals: allocation-free) ----------------
__device__ __align__(16) float g_a[(size_t)BB * TT * GG];   // LN_x(x@W_ih^T)*g_x + b_x + b
__device__ __align__(16) __nv_bfloat16 g_wih_hi[GG * II], g_wih_lo[GG * II];
__device__ __align__(16) __nv_bfloat16 g_whh_hi[GG * HH], g_whh_lo[GG * HH];

// ---------------- helpers ----------------
__device__ __forceinline__ uint32_t smem_u32(const void* p) {
    uint32_t a;
    asm("{ .reg .u64 t; cvta.to.shared.u64 t, %1; cvt.u32.u64 %0, t; }" : "=r"(a) : "l"(p));
    return a;
}
__device__ __forceinline__ void ldsm4(uint32_t* r, uint32_t a) {
    asm volatile("ldmatrix.sync.aligned.m8n8.x4.shared.b16 {%0,%1,%2,%3}, [%4];"
                 : "=r"(r[0]), "=r"(r[1]), "=r"(r[2]), "=r"(r[3]) : "r"(a));
}
__device__ __forceinline__ void mma16816(float* d, const uint32_t* a, uint32_t b0, uint32_t b1) {
    asm volatile(
        "mma.sync.aligned.m16n8k16.row.col.f32.bf16.bf16.f32 "
        "{%0,%1,%2,%3},{%4,%5,%6,%7},{%8,%9},{%0,%1,%2,%3};"
        : "+f"(d[0]), "+f"(d[1]), "+f"(d[2]), "+f"(d[3])
        : "r"(a[0]), "r"(a[1]), "r"(a[2]), "r"(a[3]), "r"(b0), "r"(b1));
}
#define CPA16(s, g) \
    asm volatile("cp.async.cg.shared.global [%0], [%1], 16;" \
                 :: "r"(s), "l"(__cvta_generic_to_global(g)) : "memory")
#define CP_COMMIT() asm volatile("cp.async.commit_group;" ::: "memory")
#define CP_WAIT1()  asm volatile("cp.async.wait_group 1;" ::: "memory")
#define CP_WAIT0()  asm volatile("cp.async.wait_group 0;" ::: "memory")

__device__ __forceinline__ float qsum(float v) {
    v += __shfl_xor_sync(0xffffffffu, v, 1);
    v += __shfl_xor_sync(0xffffffffu, v, 2);
    return v;
}
__device__ __forceinline__ float sigm(float x) { return 1.f / (1.f + __expf(-x)); }
__device__ __forceinline__ uint32_t pack2(__nv_bfloat16 lo, __nv_bfloat16 hi) {
    return (uint32_t)__bfloat16_as_ushort(lo) | ((uint32_t)__bfloat16_as_ushort(hi) << 16);
}

// ---------------- smem layouts (bytes) ----------------
// proj: A hi/lo [128 rows][264 bf16] (K=256 resident), B hi/lo [128 n][136 bf16]
#define PJ_AHI 0
#define PJ_ALO 67584
#define PJ_BHI 135168
#define PJ_BLO 169984
#define SMEM_PROJ 204800
// fused: A hi/lo [128][136 bf16], B hi/lo [128][136 bf16], a-stage [128][132 fp32]
#define FA_HI 0
#define FA_LO 34816
#define FB_HI 69632
#define FB_LO 104448
#define FA_ST 139264
#define SMEM_FUSED 206848

// ---------------- splitters (fp32 -> bf16 hi + bf16 residual) ----------------
extern "C" __global__ void split_wih(const float* __restrict__ s) {
    int i = blockIdx.x * blockDim.x + threadIdx.x;
    if (i < GG * II) {
        float v = s[i];
        __nv_bfloat16 h = __float2bfloat16(v);
        g_wih_hi[i] = h;
        g_wih_lo[i] = __float2bfloat16(v - __bfloat162float(h));
    }
}
extern "C" __global__ void split_whh(const float* __restrict__ s) {
    int i = blockIdx.x * blockDim.x + threadIdx.x;
    if (i < GG * HH) {
        float v = s[i];
        __nv_bfloat16 h = __float2bfloat16(v);
        g_whh_hi[i] = h;
        g_whh_lo[i] = __float2bfloat16(v - __bfloat162float(h));
    }
}

// ---------------- proj: g_a = LN_pergate(x @ W_ih^T)*g_x + b_x + b ----------------
extern "C" __global__ void __launch_bounds__(NTH, 1)
proj_kernel(const float* __restrict__ x, const float* __restrict__ bias,
            const float* __restrict__ gx, const float* __restrict__ bx)
{
    extern __shared__ char smc[];
    const uint32_t sb = smem_u32(smc);
    const int tid = threadIdx.x, lane = tid & 31, wid = tid >> 5;
    const int m0 = blockIdx.x * 128;
    const int wr0 = wid * 16;

#pragma unroll
    for (int it = 0; it < 16; ++it) {
        int c = tid + it * NTH;
        int row = c >> 5, k8 = (c & 31) * 8;
        const float* src = x + (size_t)(m0 + row) * II + k8;
        float4 v0 = *(const float4*)src, v1 = *(const float4*)(src + 4);
        __nv_bfloat16 h0 = __float2bfloat16(v0.x), h1 = __float2bfloat16(v0.y);
        __nv_bfloat16 h2 = __float2bfloat16(v0.z), h3 = __float2bfloat16(v0.w);
        __nv_bfloat16 h4 = __float2bfloat16(v1.x), h5 = __float2bfloat16(v1.y);
        __nv_bfloat16 h6 = __float2bfloat16(v1.z), h7 = __float2bfloat16(v1.w);
        uint4 hp, lp;
        hp.x = pack2(h0, h1); hp.y = pack2(h2, h3);
        hp.z = pack2(h4, h5); hp.w = pack2(h6, h7);
        lp.x = pack2(__float2bfloat16(v0.x - __bfloat162float(h0)),
                     __float2bfloat16(v0.y - __bfloat162float(h1)));
        lp.y = pack2(__float2bfloat16(v0.z - __bfloat162float(h2)),
                     __float2bfloat16(v0.w - __bfloat162float(h3)));
        lp.z = pack2(__float2bfloat16(v1.x - __bfloat162float(h4)),
                     __float2bfloat16(v1.y - __bfloat162float(h5)));
        lp.w = pack2(__float2bfloat16(v1.z - __bfloat162float(h6)),
                     __float2bfloat16(v1.w - __bfloat162float(h7)));
        *(uint4*)(smc + PJ_AHI + row * 528 + k8 * 2) = hp;
        *(uint4*)(smc + PJ_ALO + row * 528 + k8 * 2) = lp;
    }

    const int rA = wr0 + (lane >> 2);
    const size_t mA = (size_t)m0 + rA, mB = mA + 8;

    float acc[16][4];
#pragma unroll 1
    for (int gq = 0; gq < 4; ++gq) {
#pragma unroll
        for (int j = 0; j < 16; ++j) { acc[j][0] = acc[j][1] = acc[j][2] = acc[j][3] = 0.f; }
#pragma unroll 1
        for (int kh = 0; kh < 2; ++kh) {
#pragma unroll
            for (int it = 0; it < 8; ++it) {
                int c = tid + it * NTH;
                int n = c >> 4, k8 = (c & 15) * 8;
                size_t gi = (size_t)(gq * HH + n) * II + kh * HH + k8;
                *(uint4*)(smc + PJ_BHI + n * 272 + k8 * 2) = *(const uint4*)(g_wih_hi + gi);
                *(uint4*)(smc + PJ_BLO + n * 272 + k8 * 2) = *(const uint4*)(g_wih_lo + gi);
            }
            __syncthreads();
            const uint32_t abase = sb + PJ_AHI + (wr0 + (lane & 15)) * 528 + kh * 256 + (lane >> 4) * 16;
            const uint32_t bb0 = sb + PJ_BHI + ((lane & 7) + ((lane >> 4) << 3)) * 272 + (((lane >> 3) & 1) << 4);
#pragma unroll
            for (int ks = 0; ks < 8; ++ks) {
                uint32_t ah[4], al[4];
                ldsm4(ah, abase + ks * 32);
                ldsm4(al, abase + ks * 32 + (PJ_ALO - PJ_AHI));
#pragma unroll
                for (int g = 0; g < 8; ++g) {
                    uint32_t bh4[4], bl4[4];
                    uint32_t ba = bb0 + g * 16 * 272 + ks * 32;
                    ldsm4(bh4, ba);
                    ldsm4(bl4, ba + (PJ_BLO - PJ_BHI));
                    mma16816(acc[2 * g],     ah, bh4[0], bh4[1]);
                    mma16816(acc[2 * g + 1], ah, bh4[2], bh4[3]);
                    mma16816(acc[2 * g],     al, bh4[0], bh4[1]);
                    mma16816(acc[2 * g + 1], al, bh4[2], bh4[3]);
                    mma16816(acc[2 * g],     ah, bl4[0], bl4[1]);
                    mma16816(acc[2 * g + 1], ah, bl4[2], bl4[3]);
                }
            }
            __syncthreads();
        }
        float s0 = 0.f, q0 = 0.f, s1 = 0.f, q1 = 0.f;
#pragma unroll
        for (int j = 0; j < 16; ++j) {
            s0 += acc[j][0] + acc[j][1]; q0 += acc[j][0] * acc[j][0] + acc[j][1] * acc[j][1];
            s1 += acc[j][2] + acc[j][3]; q1 += acc[j][2] * acc[j][2] + acc[j][3] * acc[j][3];
        }
        s0 = qsum(s0); q0 = qsum(q0); s1 = qsum(s1); q1 = qsum(q1);
        const float mu0 = s0 * (1.f / HH), rs0 = rsqrtf(q0 * (1.f / HH) - mu0 * mu0 + EPSF);
        const float mu1 = s1 * (1.f / HH), rs1 = rsqrtf(q1 * (1.f / HH) - mu1 * mu1 + EPSF);
#pragma unroll
        for (int j = 0; j < 16; ++j)
#pragma unroll
            for (int e = 0; e < 4; ++e) {
                int col = 8 * j + 2 * (lane & 3) + (e & 1);
                int gcol = gq * HH + col;
                float mu = (e < 2) ? mu0 : mu1, rs = (e < 2) ? rs0 : rs1;
                size_t m = (e < 2) ? mA : mB;
                g_a[m * GG + gcol] = (acc[j][e] - mu) * rs * gx[gcol] + bx[gcol] + bias[gcol];
            }
    }
}

// ---------------- fused: all 16 LN-LSTM steps in one persistent kernel ----------------
extern "C" __global__ void __launch_bounds__(NTH, 1)
fused_kernel(const float* __restrict__ gh, const float* __restrict__ bh,
             const float* __restrict__ gc, const float* __restrict__ bc,
             const float* __restrict__ h0, const float* __restrict__ c0,
             float* __restrict__ out, int write_hn)
{
    extern __shared__ char smc[];
    const uint32_t sb = smem_u32(smc);
    const int tid = threadIdx.x, lane = tid & 31, wid = tid >> 5;
    const int m0 = blockIdx.x * 128;
    const int wr0 = wid * 16;

    // init A tile from h0 (fp32 -> bf16 hi/lo, row stride 272 B)
#pragma unroll
    for (int it = 0; it < 16; ++it) {
        int c = tid + it * NTH;
        int row = c >> 5, c4 = (c & 31) * 4;
        float4 v = *(const float4*)(h0 + (size_t)(m0 + row) * HH + c4);
        __nv_bfloat16 b0 = __float2bfloat16(v.x), b1 = __float2bfloat16(v.y);
        __nv_bfloat16 b2 = __float2bfloat16(v.z), b3 = __float2bfloat16(v.w);
        uint2 hp, lp;
        hp.x = pack2(b0, b1); hp.y = pack2(b2, b3);
        lp.x = pack2(__float2bfloat16(v.x - __bfloat162float(b0)),
                     __float2bfloat16(v.y - __bfloat162float(b1)));
        lp.y = pack2(__float2bfloat16(v.z - __bfloat162float(b2)),
                     __float2bfloat16(v.w - __bfloat162float(b3)));
        *(uint2*)(smc + FA_HI + row * 272 + c4 * 2) = hp;
        *(uint2*)(smc + FA_LO + row * 272 + c4 * 2) = lp;
    }

    const int rA = wr0 + (lane >> 2), rB = rA + 8;
    const size_t bidxA = (size_t)m0 + rA, bidxB = bidxA + 8;
    const int q2 = 2 * (lane & 3);

    // cell state carried in registers for all 16 steps
    float C[16][4];
#pragma unroll
    for (int j = 0; j < 16; ++j) {
        float2 va = *(const float2*)(c0 + bidxA * HH + 8 * j + q2);
        float2 vb = *(const float2*)(c0 + bidxB * HH + 8 * j + q2);
        C[j][0] = va.x; C[j][1] = va.y; C[j][2] = vb.x; C[j][3] = vb.y;
    }
    __syncthreads();

    float acc[16][4], S[16][4];

#pragma unroll 1
    for (int t = 0; t < TT; ++t) {
        float sc0 = 0.f, qc0 = 0.f, sc1 = 0.f, qc1 = 0.f;
#pragma unroll 1
        for (int p = 0; p < 4; ++p) {
            const int gq = (0x3120 >> (p * 4)) & 0xF;   // phase order: i(0), g(2), f(1), o(3)
            __syncthreads();                            // smem buffers free for reuse
            // B tiles via cp.async (group 0)
#pragma unroll
            for (int it = 0; it < 8; ++it) {
                int c = tid + it * NTH;
                int n = c >> 4, k8 = (c & 15) * 8;
                size_t gi = (size_t)(gq * HH + n) * HH + k8;
                CPA16(sb + FB_HI + n * 272 + k8 * 2, g_whh_hi + gi);
                CPA16(sb + FB_LO + n * 272 + k8 * 2, g_whh_lo + gi);
            }
            CP_COMMIT();
            // a_t tile for this gate chunk via cp.async (group 1, lands during MMA)
#pragma unroll
            for (int it = 0; it < 16; ++it) {
                int c = tid + it * NTH;
                int r = c >> 5, c4 = (c & 31) * 4;
                CPA16(sb + FA_ST + r * 528 + c4 * 4,
                      g_a + ((size_t)(m0 + r) * TT + t) * GG + gq * HH + c4);
            }
            CP_COMMIT();
            CP_WAIT1();                                 // B ready
            __syncthreads();

#pragma unroll
            for (int j = 0; j < 16; ++j) { acc[j][0] = acc[j][1] = acc[j][2] = acc[j][3] = 0.f; }
            const uint32_t abase = sb + FA_HI + (wr0 + (lane & 15)) * 272 + (lane >> 4) * 16;
            const uint32_t bb0 = sb + FB_HI + ((lane & 7) + ((lane >> 4) << 3)) * 272 + (((lane >> 3) & 1) << 4);
#pragma unroll
            for (int ks = 0; ks < 8; ++ks) {
                uint32_t ah[4], al[4];
                ldsm4(ah, abase + ks * 32);
                ldsm4(al, abase + ks * 32 + (FA_LO - FA_HI));
#pragma unroll
                for (int g = 0; g < 8; ++g) {
                    uint32_t bh4[4], bl4[4];
                    uint32_t ba = bb0 + g * 16 * 272 + ks * 32;
                    ldsm4(bh4, ba);
                    ldsm4(bl4, ba + (FB_LO - FB_HI));
                    mma16816(acc[2 * g],     ah, bh4[0], bh4[1]);
                    mma16816(acc[2 * g + 1], ah, bh4[2], bh4[3]);
                    mma16816(acc[2 * g],     al, bh4[0], bh4[1]);
                    mma16816(acc[2 * g + 1], al, bh4[2], bh4[3]);
                    mma16816(acc[2 * g],     ah, bl4[0], bl4[1]);
                    mma16816(acc[2 * g + 1], ah, bl4[2], bl4[3]);
                }
            }
            CP_WAIT0();                                 // a_t staged
            __syncthreads();

            // gate-LN stats
            float s0 = 0.f, q0 = 0.f, s1 = 0.f, q1 = 0.f;
#pragma unroll
            for (int j = 0; j < 16; ++j) {
                s0 += acc[j][0] + acc[j][1]; q0 += acc[j][0] * acc[j][0] + acc[j][1] * acc[j][1];
                s1 += acc[j][2] + acc[j][3]; q1 += acc[j][2] * acc[j][2] + acc[j][3] * acc[j][3];
            }
            s0 = qsum(s0); q0 = qsum(q0); s1 = qsum(s1); q1 = qsum(q1);
            const float mu0 = s0 * (1.f / HH), rs0 = rsqrtf(q0 * (1.f / HH) - mu0 * mu0 + EPSF);
            const float mu1 = s1 * (1.f / HH), rs1 = rsqrtf(q1 * (1.f / HH) - mu1 * mu1 + EPSF);

#pragma unroll
            for (int j = 0; j < 16; ++j) {
                int col = 8 * j + q2;
                float2 aA = *(const float2*)(smc + FA_ST + rA * 528 + col * 4);
                float2 aB = *(const float2*)(smc + FA_ST + rB * 528 + col * 4);
                float ar[4] = {aA.x, aA.y, aB.x, aB.y};
#pragma unroll
                for (int e = 0; e < 4; ++e) {
                    int gcol = gq * HH + col + (e & 1);
                    float mu = (e < 2) ? mu0 : mu1, rs = (e < 2) ? rs0 : rs1;
                    float gn = (acc[j][e] - mu) * rs * gh[gcol] + bh[gcol] + ar[e];
                    if (p == 0) {
                        S[j][e] = sigm(gn);
                    } else if (p == 1) {
                        S[j][e] *= tanhf(gn);
                    } else if (p == 2) {
                        float cv = sigm(gn) * C[j][e] + S[j][e];
                        C[j][e] = cv;
                        if (e < 2) { sc0 += cv; qc0 += cv * cv; }
                        else       { sc1 += cv; qc1 += cv * cv; }
                    } else {
                        acc[j][e] = sigm(gn);            // sigma(o)
                    }
                }
            }
        }

        // cell-LN + outputs + h -> smem A (bf16 hi/lo) for next step
        sc0 = qsum(sc0); qc0 = qsum(qc0); sc1 = qsum(sc1); qc1 = qsum(qc1);
        const float mc0 = sc0 * (1.f / HH), rc0 = rsqrtf(qc0 * (1.f / HH) - mc0 * mc0 + EPSF);
        const float mc1 = sc1 * (1.f / HH), rc1 = rsqrtf(qc1 * (1.f / HH) - mc1 * mc1 + EPSF);
        float* oA = out + (bidxA * TT + t) * HH;
        float* oB = out + (bidxB * TT + t) * HH;
#pragma unroll
        for (int j = 0; j < 16; ++j) {
            int col = 8 * j + q2;
            float hv[4];
#pragma unroll
            for (int e = 0; e < 4; ++e) {
                int cc = col + (e & 1);
                float mc = (e < 2) ? mc0 : mc1, rc = (e < 2) ? rc0 : rc1;
                float cl = (C[j][e] - mc) * rc * gc[cc] + bc[cc];
                hv[e] = acc[j][e] * tanhf(cl);
            }
            *(float2*)(oA + col) = make_float2(hv[0], hv[1]);
            *(float2*)(oB + col) = make_float2(hv[2], hv[3]);
            if (write_hn && t == TT - 1) {
                *(float2*)(out + (size_t)BB * TT * HH + bidxA * HH + col) = make_float2(hv[0], hv[1]);
                *(float2*)(out + (size_t)BB * TT * HH + bidxB * HH + col) = make_float2(hv[2], hv[3]);
            }
            __nv_bfloat16 b0 = __float2bfloat16(hv[0]), b1 = __float2bfloat16(hv[1]);
            __nv_bfloat16 b2 = __float2bfloat16(hv[2]), b3 = __float2bfloat16(hv[3]);
            *(uint32_t*)(smc + FA_HI + rA * 272 + col * 2) = pack2(b0, b1);
            *(uint32_t*)(smc + FA_HI + rB * 272 + col * 2) = pack2(b2, b3);
            *(uint32_t*)(smc + FA_LO + rA * 272 + col * 2) =
                pack2(__float2bfloat16(hv[0] - __bfloat162float(b0)),
                      __float2bfloat16(hv[1] - __bfloat162float(b1)));
            *(uint32_t*)(smc + FA_LO + rB * 272 + col * 2) =
                pack2(__float2bfloat16(hv[2] - __bfloat162float(b2)),
                      __float2bfloat16(hv[3] - __bfloat162float(b3)));
        }
        // next iteration's leading __syncthreads orders these stores before ldsm reads
    }
}

// ---------------- host ----------------
extern "C" void kernel_launch(void* const* d_in, const int* in_sizes, int n_in,
                              void* d_out, int out_size)
{
    const float* x    = (const float*)d_in[0];
    const float* h0   = (const float*)d_in[1];
    const float* c0   = (const float*)d_in[2];
    const float* W_ih = (const float*)d_in[3];
    const float* W_hh = (const float*)d_in[4];
    const float* bias = (const float*)d_in[5];
    const float* g_x  = (const float*)d_in[6];
    const float* b_x  = (const float*)d_in[7];
    const float* gh   = (const float*)d_in[8];
    const float* bh   = (const float*)d_in[9];
    const float* gc   = (const float*)d_in[10];
    const float* bc   = (const float*)d_in[11];
    float* out = (float*)d_out;

    cudaFuncSetAttribute(proj_kernel,  cudaFuncAttributeMaxDynamicSharedMemorySize, SMEM_PROJ);
    cudaFuncSetAttribute(fused_kernel, cudaFuncAttributeMaxDynamicSharedMemorySize, SMEM_FUSED);

    split_wih<<<(GG * II + 255) / 256, 256>>>(W_ih);
    split_whh<<<(GG * HH + 255) / 256, 256>>>(W_hh);

    proj_kernel<<<(BB * TT) / 128, NTH, SMEM_PROJ>>>(x, bias, g_x, b_x);

    const long long need = (long long)BB * TT * HH + (long long)BB * HH;
    const int write_full = (out_size >= need) ? 1 : 0;

    fused_kernel<<<BB / 128, NTH, SMEM_FUSED>>>(gh, bh, gc, bc, h0, c0, out, write_full);
}

// round 9
// speedup vs baseline: 5.1904x; 1.2144x over previous
#include <cuda_runtime.h>
#include <cuda_bf16.h>
#include <cstdint>

#define BB 16384
#define TT 16
#define II 256
#define HH 128
#define GG 512
#define EPSF 1e-5f
#define NTH 256
#define NTF 512

// ---------------- scratch (device globals: allocation-free) ----------------
__device__ __align__(16) float g_a[(size_t)BB * TT * GG];   // LN_x(x@W_ih^T)*g_x + b_x + b
__device__ __align__(16) __nv_bfloat16 g_wih_hi[GG * II], g_wih_lo[GG * II];
__device__ __align__(16) __nv_bfloat16 g_whh_hi[GG * HH], g_whh_lo[GG * HH];

// ---------------- helpers ----------------
__device__ __forceinline__ uint32_t smem_u32(const void* p) {
    uint32_t a;
    asm("{ .reg .u64 t; cvta.to.shared.u64 t, %1; cvt.u32.u64 %0, t; }" : "=r"(a) : "l"(p));
    return a;
}
__device__ __forceinline__ void ldsm4(uint32_t* r, uint32_t a) {
    asm volatile("ldmatrix.sync.aligned.m8n8.x4.shared.b16 {%0,%1,%2,%3}, [%4];"
                 : "=r"(r[0]), "=r"(r[1]), "=r"(r[2]), "=r"(r[3]) : "r"(a));
}
__device__ __forceinline__ void mma16816(float* d, const uint32_t* a, uint32_t b0, uint32_t b1) {
    asm volatile(
        "mma.sync.aligned.m16n8k16.row.col.f32.bf16.bf16.f32 "
        "{%0,%1,%2,%3},{%4,%5,%6,%7},{%8,%9},{%0,%1,%2,%3};"
        : "+f"(d[0]), "+f"(d[1]), "+f"(d[2]), "+f"(d[3])
        : "r"(a[0]), "r"(a[1]), "r"(a[2]), "r"(a[3]), "r"(b0), "r"(b1));
}
#define CPA16(s, g) \
    asm volatile("cp.async.cg.shared.global [%0], [%1], 16;" \
                 :: "r"(s), "l"(__cvta_generic_to_global(g)) : "memory")
#define CP_COMMIT() asm volatile("cp.async.commit_group;" ::: "memory")
#define CP_WAIT0()  asm volatile("cp.async.wait_group 0;" ::: "memory")

__device__ __forceinline__ float qsum(float v) {
    v += __shfl_xor_sync(0xffffffffu, v, 1);
    v += __shfl_xor_sync(0xffffffffu, v, 2);
    return v;
}
__device__ __forceinline__ float sigm(float x) { return 1.f / (1.f + __expf(-x)); }
__device__ __forceinline__ uint32_t pack2(__nv_bfloat16 lo, __nv_bfloat16 hi) {
    return (uint32_t)__bfloat16_as_ushort(lo) | ((uint32_t)__bfloat16_as_ushort(hi) << 16);
}

// ---------------- smem layouts (bytes) ----------------
// proj (unchanged from R8)
#define PJ_AHI 0
#define PJ_ALO 67584
#define PJ_BHI 135168
#define PJ_BLO 169984
#define SMEM_PROJ 204800
// fused v2: A hi/lo [128][136 bf16]; B ring x2 (hi+lo) [128][136]; red 2KB
#define F_AHI 0
#define F_ALO 34816
#define F_B0  69632
#define F_B1  139264
#define F_RED 208896
#define SMEM_FUSED 210944

// ---------------- splitters (fp32 -> bf16 hi + bf16 residual) ----------------
extern "C" __global__ void split_wih(const float* __restrict__ s) {
    int i = blockIdx.x * blockDim.x + threadIdx.x;
    if (i < GG * II) {
        float v = s[i];
        __nv_bfloat16 h = __float2bfloat16(v);
        g_wih_hi[i] = h;
        g_wih_lo[i] = __float2bfloat16(v - __bfloat162float(h));
    }
}
extern "C" __global__ void split_whh(const float* __restrict__ s) {
    int i = blockIdx.x * blockDim.x + threadIdx.x;
    if (i < GG * HH) {
        float v = s[i];
        __nv_bfloat16 h = __float2bfloat16(v);
        g_whh_hi[i] = h;
        g_whh_lo[i] = __float2bfloat16(v - __bfloat162float(h));
    }
}

// ---------------- proj: g_a = LN_pergate(x @ W_ih^T)*g_x + b_x + b ----------------
extern "C" __global__ void __launch_bounds__(NTH, 1)
proj_kernel(const float* __restrict__ x, const float* __restrict__ bias,
            const float* __restrict__ gx, const float* __restrict__ bx)
{
    extern __shared__ char smc[];
    const uint32_t sb = smem_u32(smc);
    const int tid = threadIdx.x, lane = tid & 31, wid = tid >> 5;
    const int m0 = blockIdx.x * 128;
    const int wr0 = wid * 16;

#pragma unroll
    for (int it = 0; it < 16; ++it) {
        int c = tid + it * NTH;
        int row = c >> 5, k8 = (c & 31) * 8;
        const float* src = x + (size_t)(m0 + row) * II + k8;
        float4 v0 = *(const float4*)src, v1 = *(const float4*)(src + 4);
        __nv_bfloat16 h0 = __float2bfloat16(v0.x), h1 = __float2bfloat16(v0.y);
        __nv_bfloat16 h2 = __float2bfloat16(v0.z), h3 = __float2bfloat16(v0.w);
        __nv_bfloat16 h4 = __float2bfloat16(v1.x), h5 = __float2bfloat16(v1.y);
        __nv_bfloat16 h6 = __float2bfloat16(v1.z), h7 = __float2bfloat16(v1.w);
        uint4 hp, lp;
        hp.x = pack2(h0, h1); hp.y = pack2(h2, h3);
        hp.z = pack2(h4, h5); hp.w = pack2(h6, h7);
        lp.x = pack2(__float2bfloat16(v0.x - __bfloat162float(h0)),
                     __float2bfloat16(v0.y - __bfloat162float(h1)));
        lp.y = pack2(__float2bfloat16(v0.z - __bfloat162float(h2)),
                     __float2bfloat16(v0.w - __bfloat162float(h3)));
        lp.z = pack2(__float2bfloat16(v1.x - __bfloat162float(h4)),
                     __float2bfloat16(v1.y - __bfloat162float(h5)));
        lp.w = pack2(__float2bfloat16(v1.z - __bfloat162float(h6)),
                     __float2bfloat16(v1.w - __bfloat162float(h7)));
        *(uint4*)(smc + PJ_AHI + row * 528 + k8 * 2) = hp;
        *(uint4*)(smc + PJ_ALO + row * 528 + k8 * 2) = lp;
    }

    const int rA = wr0 + (lane >> 2);
    const size_t mA = (size_t)m0 + rA, mB = mA + 8;

    float acc[16][4];
#pragma unroll 1
    for (int gq = 0; gq < 4; ++gq) {
#pragma unroll
        for (int j = 0; j < 16; ++j) { acc[j][0] = acc[j][1] = acc[j][2] = acc[j][3] = 0.f; }
#pragma unroll 1
        for (int kh = 0; kh < 2; ++kh) {
#pragma unroll
            for (int it = 0; it < 8; ++it) {
                int c = tid + it * NTH;
                int n = c >> 4, k8 = (c & 15) * 8;
                size_t gi = (size_t)(gq * HH + n) * II + kh * HH + k8;
                *(uint4*)(smc + PJ_BHI + n * 272 + k8 * 2) = *(const uint4*)(g_wih_hi + gi);
                *(uint4*)(smc + PJ_BLO + n * 272 + k8 * 2) = *(const uint4*)(g_wih_lo + gi);
            }
            __syncthreads();
            const uint32_t abase = sb + PJ_AHI + (wr0 + (lane & 15)) * 528 + kh * 256 + (lane >> 4) * 16;
            const uint32_t bb0 = sb + PJ_BHI + ((lane & 7) + ((lane >> 4) << 3)) * 272 + (((lane >> 3) & 1) << 4);
#pragma unroll
            for (int ks = 0; ks < 8; ++ks) {
                uint32_t ah[4], al[4];
                ldsm4(ah, abase + ks * 32);
                ldsm4(al, abase + ks * 32 + (PJ_ALO - PJ_AHI));
#pragma unroll
                for (int g = 0; g < 8; ++g) {
                    uint32_t bh4[4], bl4[4];
                    uint32_t ba = bb0 + g * 16 * 272 + ks * 32;
                    ldsm4(bh4, ba);
                    ldsm4(bl4, ba + (PJ_BLO - PJ_BHI));
                    mma16816(acc[2 * g],     ah, bh4[0], bh4[1]);
                    mma16816(acc[2 * g + 1], ah, bh4[2], bh4[3]);
                    mma16816(acc[2 * g],     al, bh4[0], bh4[1]);
                    mma16816(acc[2 * g + 1], al, bh4[2], bh4[3]);
                    mma16816(acc[2 * g],     ah, bl4[0], bl4[1]);
                    mma16816(acc[2 * g + 1], ah, bl4[2], bl4[3]);
                }
            }
            __syncthreads();
        }
        float s0 = 0.f, q0 = 0.f, s1 = 0.f, q1 = 0.f;
#pragma unroll
        for (int j = 0; j < 16; ++j) {
            s0 += acc[j][0] + acc[j][1]; q0 += acc[j][0] * acc[j][0] + acc[j][1] * acc[j][1];
            s1 += acc[j][2] + acc[j][3]; q1 += acc[j][2] * acc[j][2] + acc[j][3] * acc[j][3];
        }
        s0 = qsum(s0); q0 = qsum(q0); s1 = qsum(s1); q1 = qsum(q1);
        const float mu0 = s0 * (1.f / HH), rs0 = rsqrtf(q0 * (1.f / HH) - mu0 * mu0 + EPSF);
        const float mu1 = s1 * (1.f / HH), rs1 = rsqrtf(q1 * (1.f / HH) - mu1 * mu1 + EPSF);
#pragma unroll
        for (int j = 0; j < 16; ++j)
#pragma unroll
            for (int e = 0; e < 4; ++e) {
                int col = 8 * j + 2 * (lane & 3) + (e & 1);
                int gcol = gq * HH + col;
                float mu = (e < 2) ? mu0 : mu1, rs = (e < 2) ? rs0 : rs1;
                size_t m = (e < 2) ? mA : mB;
                g_a[m * GG + gcol] = (acc[j][e] - mu) * rs * gx[gcol] + bx[gcol] + bias[gcol];
            }
    }
}

// ---------------- fused v2: 16 steps, 16 warps, N-split, ring-buffered B ----------------
__device__ __forceinline__ void issue_B(uint32_t sb, int tid, int gq, int buf) {
    const uint32_t base = sb + (buf ? F_B1 : F_B0);
#pragma unroll
    for (int it = 0; it < 8; ++it) {
        int c = tid + it * NTF;                 // 4096 chunks: 2048 hi + 2048 lo
        int part = c >> 11, cc = c & 2047;
        int n = cc >> 4, k8 = (cc & 15) * 8;
        const __nv_bfloat16* src = (part ? g_whh_lo : g_whh_hi) + (size_t)(gq * HH + n) * HH + k8;
        CPA16(base + part * 34816 + n * 272 + k8 * 2, src);
    }
    CP_COMMIT();
}

extern "C" __global__ void __launch_bounds__(NTF, 1)
fused_kernel(const float* __restrict__ gh, const float* __restrict__ bh,
             const float* __restrict__ gc, const float* __restrict__ bc,
             const float* __restrict__ h0, const float* __restrict__ c0,
             float* __restrict__ out, int write_hn)
{
    extern __shared__ char smc[];
    const uint32_t sb = smem_u32(smc);
    const int tid = threadIdx.x, lane = tid & 31, wid = tid >> 5;
    const int m0 = blockIdx.x * 128;
    const int wr0 = (wid >> 1) * 16;            // row group
    const int half = wid & 1, cb = half * 64;   // N half
    float2* red = (float2*)(smc + F_RED);

    // A init from h0 (fp32 -> bf16 hi/lo)
#pragma unroll
    for (int it = 0; it < 8; ++it) {
        int c = tid + it * NTF;
        int row = c >> 5, c4 = (c & 31) * 4;
        float4 v = *(const float4*)(h0 + (size_t)(m0 + row) * HH + c4);
        __nv_bfloat16 b0 = __float2bfloat16(v.x), b1 = __float2bfloat16(v.y);
        __nv_bfloat16 b2 = __float2bfloat16(v.z), b3 = __float2bfloat16(v.w);
        uint2 hp, lp;
        hp.x = pack2(b0, b1); hp.y = pack2(b2, b3);
        lp.x = pack2(__float2bfloat16(v.x - __bfloat162float(b0)),
                     __float2bfloat16(v.y - __bfloat162float(b1)));
        lp.y = pack2(__float2bfloat16(v.z - __bfloat162float(b2)),
                     __float2bfloat16(v.w - __bfloat162float(b3)));
        *(uint2*)(smc + F_AHI + row * 272 + c4 * 2) = hp;
        *(uint2*)(smc + F_ALO + row * 272 + c4 * 2) = lp;
    }

    const int rA = wr0 + (lane >> 2), rB = rA + 8;
    const size_t bidxA = (size_t)m0 + rA, bidxB = bidxA + 8;
    const int q2 = 2 * (lane & 3);

    float C[8][4];
#pragma unroll
    for (int j = 0; j < 8; ++j) {
        float2 va = *(const float2*)(c0 + bidxA * HH + cb + 8 * j + q2);
        float2 vb = *(const float2*)(c0 + bidxB * HH + cb + 8 * j + q2);
        C[j][0] = va.x; C[j][1] = va.y; C[j][2] = vb.x; C[j][3] = vb.y;
    }

    issue_B(sb, tid, 0, 0);                     // prologue: B for (t=0, i-gate)

    float acc[8][4], S[8][4];

#pragma unroll 1
    for (int t = 0; t < TT; ++t) {
        float sc0 = 0.f, qc0 = 0.f, sc1 = 0.f, qc1 = 0.f;
#pragma unroll 1
        for (int p = 0; p < 4; ++p) {
            const int pc = t * 4 + p, buf = pc & 1;
            const int gq = (0x3120 >> (p * 4)) & 0xF;   // i(0), g(2), f(1), o(3)
            CP_WAIT0();
            __syncthreads();                    // B ready; orders prior epilogue stores

            // a_t prefetch into registers (independent of MMA)
            const float* aA = g_a + ((size_t)bidxA * TT + t) * GG + gq * HH + cb;
            const float* aB = g_a + ((size_t)bidxB * TT + t) * GG + gq * HH + cb;
            float2 apA[8], apB[8];
#pragma unroll
            for (int j = 0; j < 8; ++j) {
                apA[j] = *(const float2*)(aA + 8 * j + q2);
                apB[j] = *(const float2*)(aB + 8 * j + q2);
            }

#pragma unroll
            for (int j = 0; j < 8; ++j) { acc[j][0] = acc[j][1] = acc[j][2] = acc[j][3] = 0.f; }
            const uint32_t abase = sb + F_AHI + (wr0 + (lane & 15)) * 272 + ((lane >> 4) << 4);
            const uint32_t bb0 = sb + (buf ? F_B1 : F_B0)
                               + (cb + (lane & 7) + ((lane >> 4) << 3)) * 272 + (((lane >> 3) & 1) << 4);
#pragma unroll
            for (int ks = 0; ks < 8; ++ks) {
                uint32_t ah[4], al[4];
                ldsm4(ah, abase + ks * 32);
                ldsm4(al, abase + ks * 32 + (F_ALO - F_AHI));
#pragma unroll
                for (int g = 0; g < 4; ++g) {
                    uint32_t bh4[4], bl4[4];
                    uint32_t ba = bb0 + g * 16 * 272 + ks * 32;
                    ldsm4(bh4, ba);
                    ldsm4(bl4, ba + 34816);
                    mma16816(acc[2 * g],     ah, bh4[0], bh4[1]);
                    mma16816(acc[2 * g + 1], ah, bh4[2], bh4[3]);
                    mma16816(acc[2 * g],     al, bh4[0], bh4[1]);
                    mma16816(acc[2 * g + 1], al, bh4[2], bh4[3]);
                    mma16816(acc[2 * g],     ah, bl4[0], bl4[1]);
                    mma16816(acc[2 * g + 1], ah, bl4[2], bl4[3]);
                }
            }
            // prefetch next phase's B into the other ring slot (lands during epilogue)
            if (pc + 1 < 4 * TT)
                issue_B(sb, tid, (0x3120 >> (((p + 1) & 3) * 4)) & 0xF, (pc + 1) & 1);

            // gate-LN stats: own 64-col partials, combine across halves via smem
            float s0 = 0.f, q0 = 0.f, s1 = 0.f, q1 = 0.f;
#pragma unroll
            for (int j = 0; j < 8; ++j) {
                s0 += acc[j][0] + acc[j][1]; q0 += acc[j][0] * acc[j][0] + acc[j][1] * acc[j][1];
                s1 += acc[j][2] + acc[j][3]; q1 += acc[j][2] * acc[j][2] + acc[j][3] * acc[j][3];
            }
            s0 = qsum(s0); q0 = qsum(q0); s1 = qsum(s1); q1 = qsum(q1);
            if ((lane & 3) == 0) {
                red[rA * 2 + half] = make_float2(s0, q0);
                red[rB * 2 + half] = make_float2(s1, q1);
            }
            __syncthreads();
            {
                float2 o0 = red[rA * 2 + (1 - half)], o1 = red[rB * 2 + (1 - half)];
                s0 += o0.x; q0 += o0.y; s1 += o1.x; q1 += o1.y;
            }
            const float mu0 = s0 * (1.f / HH), rs0 = rsqrtf(q0 * (1.f / HH) - mu0 * mu0 + EPSF);
            const float mu1 = s1 * (1.f / HH), rs1 = rsqrtf(q1 * (1.f / HH) - mu1 * mu1 + EPSF);

#pragma unroll
            for (int j = 0; j < 8; ++j) {
                int colb = cb + 8 * j + q2;
                float2 gh2 = *(const float2*)(gh + gq * HH + colb);
                float2 bh2 = *(const float2*)(bh + gq * HH + colb);
                float ar[4] = {apA[j].x, apA[j].y, apB[j].x, apB[j].y};
#pragma unroll
                for (int e = 0; e < 4; ++e) {
                    float mu = (e < 2) ? mu0 : mu1, rs = (e < 2) ? rs0 : rs1;
                    float gv = (e & 1) ? gh2.y : gh2.x;
                    float bv = (e & 1) ? bh2.y : bh2.x;
                    float gn = (acc[j][e] - mu) * rs * gv + bv + ar[e];
                    if (p == 0) {
                        S[j][e] = sigm(gn);
                    } else if (p == 1) {
                        S[j][e] *= tanhf(gn);
                    } else if (p == 2) {
                        float cv = sigm(gn) * C[j][e] + S[j][e];
                        C[j][e] = cv;
                        if (e < 2) { sc0 += cv; qc0 += cv * cv; }
                        else       { sc1 += cv; qc1 += cv * cv; }
                    } else {
                        acc[j][e] = sigm(gn);            // sigma(o)
                    }
                }
            }
        }

        // cell-LN (cross-half combine) + outputs + h writeback to A tile
        __syncthreads();                        // all gate-o red reads done
        sc0 = qsum(sc0); qc0 = qsum(qc0); sc1 = qsum(sc1); qc1 = qsum(qc1);
        if ((lane & 3) == 0) {
            red[rA * 2 + half] = make_float2(sc0, qc0);
            red[rB * 2 + half] = make_float2(sc1, qc1);
        }
        __syncthreads();
        {
            float2 o0 = red[rA * 2 + (1 - half)], o1 = red[rB * 2 + (1 - half)];
            sc0 += o0.x; qc0 += o0.y; sc1 += o1.x; qc1 += o1.y;
        }
        const float mc0 = sc0 * (1.f / HH), rc0 = rsqrtf(qc0 * (1.f / HH) - mc0 * mc0 + EPSF);
        const float mc1 = sc1 * (1.f / HH), rc1 = rsqrtf(qc1 * (1.f / HH) - mc1 * mc1 + EPSF);
        float* oA = out + (bidxA * TT + t) * HH;
        float* oB = out + (bidxB * TT + t) * HH;
#pragma unroll
        for (int j = 0; j < 8; ++j) {
            int colb = cb + 8 * j + q2;
            float2 gc2 = *(const float2*)(gc + colb);
            float2 bc2 = *(const float2*)(bc + colb);
            float hv[4];
#pragma unroll
            for (int e = 0; e < 4; ++e) {
                float mc = (e < 2) ? mc0 : mc1, rc = (e < 2) ? rc0 : rc1;
                float gv = (e & 1) ? gc2.y : gc2.x;
                float bv = (e & 1) ? bc2.y : bc2.x;
                float cl = (C[j][e] - mc) * rc * gv + bv;
                hv[e] = acc[j][e] * tanhf(cl);
            }
            *(float2*)(oA + colb) = make_float2(hv[0], hv[1]);
            *(float2*)(oB + colb) = make_float2(hv[2], hv[3]);
            if (write_hn && t == TT - 1) {
                *(float2*)(out + (size_t)BB * TT * HH + bidxA * HH + colb) = make_float2(hv[0], hv[1]);
                *(float2*)(out + (size_t)BB * TT * HH + bidxB * HH + colb) = make_float2(hv[2], hv[3]);
            }
            __nv_bfloat16 b0 = __float2bfloat16(hv[0]), b1 = __float2bfloat16(hv[1]);
            __nv_bfloat16 b2 = __float2bfloat16(hv[2]), b3 = __float2bfloat16(hv[3]);
            *(uint32_t*)(smc + F_AHI + rA * 272 + colb * 2) = pack2(b0, b1);
            *(uint32_t*)(smc + F_AHI + rB * 272 + colb * 2) = pack2(b2, b3);
            *(uint32_t*)(smc + F_ALO + rA * 272 + colb * 2) =
                pack2(__float2bfloat16(hv[0] - __bfloat162float(b0)),
                      __float2bfloat16(hv[1] - __bfloat162float(b1)));
            *(uint32_t*)(smc + F_ALO + rB * 272 + colb * 2) =
                pack2(__float2bfloat16(hv[2] - __bfloat162float(b2)),
                      __float2bfloat16(hv[3] - __bfloat162float(b3)));
        }
        // next phase's leading __syncthreads orders these A-tile stores before ldsm
    }
}

// ---------------- host ----------------
extern "C" void kernel_launch(void* const* d_in, const int* in_sizes, int n_in,
                              void* d_out, int out_size)
{
    const float* x    = (const float*)d_in[0];
    const float* h0   = (const float*)d_in[1];
    const float* c0   = (const float*)d_in[2];
    const float* W_ih = (const float*)d_in[3];
    const float* W_hh = (const float*)d_in[4];
    const float* bias = (const float*)d_in[5];
    const float* g_x  = (const float*)d_in[6];
    const float* b_x  = (const float*)d_in[7];
    const float* gh   = (const float*)d_in[8];
    const float* bh   = (const float*)d_in[9];
    const float* gc   = (const float*)d_in[10];
    const float* bc   = (const float*)d_in[11];
    float* out = (float*)d_out;

    cudaFuncSetAttribute(proj_kernel,  cudaFuncAttributeMaxDynamicSharedMemorySize, SMEM_PROJ);
    cudaFuncSetAttribute(fused_kernel, cudaFuncAttributeMaxDynamicSharedMemorySize, SMEM_FUSED);

    split_wih<<<(GG * II + 255) / 256, 256>>>(W_ih);
    split_whh<<<(GG * HH + 255) / 256, 256>>>(W_hh);

    proj_kernel<<<(BB * TT) / 128, NTH, SMEM_PROJ>>>(x, bias, g_x, b_x);

    const long long need = (long long)BB * TT * HH + (long long)BB * HH;
    const int write_full = (out_size >= need) ? 1 : 0;

    fused_kernel<<<BB / 128, NTF, SMEM_FUSED>>>(gh, bh, gc, bc, h0, c0, out, write_full);
}